// round 2
// baseline (speedup 1.0000x reference)
#include <cuda_runtime.h>
#include <cstdint>

#define DMODEL 1024
#define NHEADS 16
#define DKH    64

// Scratch (allocation-free rule: __device__ globals). 4 x 16 MB.
__device__ float g_Q[4096 * 1024];
__device__ float g_K[4096 * 1024];
__device__ float g_V[4096 * 1024];
__device__ float g_X[4096 * 1024];

// ---------------------------------------------------------------------------
// C[M,N] = A[M,K] @ B[N,K]^T   (both operands K-contiguous, row-major)
// 128x128 block, BK=16, 256 threads, 8x8 register microtile.
// ---------------------------------------------------------------------------
__global__ __launch_bounds__(256) void sgemm_nt_128(
    const float* __restrict__ A, const float* __restrict__ B,
    float* __restrict__ C, int M, int N, int K)
{
    __shared__ float As[128][17];   // [m][k], padded
    __shared__ float Bs[16][128];   // [k][n], transposed on load

    const int tid = threadIdx.x;
    const int tx = tid & 15, ty = tid >> 4;
    const int m0 = blockIdx.y * 128, n0 = blockIdx.x * 128;

    float acc[8][8];
    #pragma unroll
    for (int i = 0; i < 8; i++)
        #pragma unroll
        for (int j = 0; j < 8; j++) acc[i][j] = 0.f;

    for (int k0 = 0; k0 < K; k0 += 16) {
        #pragma unroll
        for (int s = 0; s < 2; s++) {
            int f = tid + s * 256;          // 0..511
            int r = f >> 2, c = (f & 3) << 2;
            float4 av = *(const float4*)(A + (size_t)(m0 + r) * K + k0 + c);
            As[r][c + 0] = av.x; As[r][c + 1] = av.y;
            As[r][c + 2] = av.z; As[r][c + 3] = av.w;
            float4 bv = *(const float4*)(B + (size_t)(n0 + r) * K + k0 + c);
            Bs[c + 0][r] = bv.x; Bs[c + 1][r] = bv.y;
            Bs[c + 2][r] = bv.z; Bs[c + 3][r] = bv.w;
        }
        __syncthreads();

        #pragma unroll
        for (int kk = 0; kk < 16; kk++) {
            float a[8], bb[8];
            #pragma unroll
            for (int i = 0; i < 8; i++) a[i] = As[ty * 8 + i][kk];
            float4 b0 = *(const float4*)&Bs[kk][tx * 8];
            float4 b1 = *(const float4*)&Bs[kk][tx * 8 + 4];
            bb[0] = b0.x; bb[1] = b0.y; bb[2] = b0.z; bb[3] = b0.w;
            bb[4] = b1.x; bb[5] = b1.y; bb[6] = b1.z; bb[7] = b1.w;
            #pragma unroll
            for (int i = 0; i < 8; i++)
                #pragma unroll
                for (int j = 0; j < 8; j++)
                    acc[i][j] = fmaf(a[i], bb[j], acc[i][j]);
        }
        __syncthreads();
    }

    #pragma unroll
    for (int i = 0; i < 8; i++) {
        float* cp = C + (size_t)(m0 + ty * 8 + i) * N + n0 + tx * 8;
        *(float4*)cp       = make_float4(acc[i][0], acc[i][1], acc[i][2], acc[i][3]);
        *(float4*)(cp + 4) = make_float4(acc[i][4], acc[i][5], acc[i][6], acc[i][7]);
    }
}

// ---------------------------------------------------------------------------
// Flash attention, fp32. One CTA per (b, h, 128-query tile).
// Streams 128-key tiles; online softmax; P staged via SMEM for PV GEMM.
// Mask is read as 32-bit words (covers int32 and float32 encodings of bool).
// ---------------------------------------------------------------------------
struct AttnSmem {
    float Qs[128][65];    // [q][d]
    float Kst[64][128];   // [d][k]  (transposed K tile)
    float Vs[128][68];    // [k][d]
    float Ps[128][132];   // P = exp(scores)
    float red[128][16];   // row-reduction scratch
    float mrow[128];
    float lrow[128];
    float alph[128];
};

__global__ __launch_bounds__(256) void flash_attn_f32(
    const int* __restrict__ mask, int S)
{
    extern __shared__ char smraw[];
    AttnSmem& sm = *reinterpret_cast<AttnSmem*>(smraw);

    const int tid = threadIdx.x;
    const int tx = tid & 15, ty = tid >> 4;
    const int b = blockIdx.z, h = blockIdx.y;
    const int q0 = blockIdx.x * 128;

    // Load Q tile [128 x 64] once.
    const float* Qg = g_Q + ((size_t)b * S + q0) * DMODEL + h * DKH;
    #pragma unroll
    for (int s = 0; s < 8; s++) {
        int f = tid + s * 256;
        int r = f >> 4, c = (f & 15) << 2;
        float4 v = *(const float4*)(Qg + (size_t)r * DMODEL + c);
        sm.Qs[r][c + 0] = v.x; sm.Qs[r][c + 1] = v.y;
        sm.Qs[r][c + 2] = v.z; sm.Qs[r][c + 3] = v.w;
    }
    if (tid < 128) { sm.mrow[tid] = -3.0e38f; sm.lrow[tid] = 0.f; }

    float oacc[8][4];
    #pragma unroll
    for (int i = 0; i < 8; i++)
        #pragma unroll
        for (int j = 0; j < 4; j++) oacc[i][j] = 0.f;

    // mask layout [B, 1, S, S], 32-bit elements
    const int* Mb = mask + (size_t)b * S * S + (size_t)q0 * S;
    __syncthreads();

    for (int k0 = 0; k0 < S; k0 += 128) {
        // Load K (transposed) and V tiles.
        const float* Kg = g_K + ((size_t)b * S + k0) * DMODEL + h * DKH;
        const float* Vg = g_V + ((size_t)b * S + k0) * DMODEL + h * DKH;
        #pragma unroll
        for (int s = 0; s < 8; s++) {
            int f = tid + s * 256;
            int r = f >> 4, c = (f & 15) << 2;
            float4 kv = *(const float4*)(Kg + (size_t)r * DMODEL + c);
            sm.Kst[c + 0][r] = kv.x; sm.Kst[c + 1][r] = kv.y;
            sm.Kst[c + 2][r] = kv.z; sm.Kst[c + 3][r] = kv.w;
            float4 vv = *(const float4*)(Vg + (size_t)r * DMODEL + c);
            *(float4*)&sm.Vs[r][c] = vv;
        }
        __syncthreads();

        // Scores S = Q K^T  (8x8 per thread over [128q x 128k]).
        float sreg[8][8];
        #pragma unroll
        for (int i = 0; i < 8; i++)
            #pragma unroll
            for (int j = 0; j < 8; j++) sreg[i][j] = 0.f;

        #pragma unroll 4
        for (int d = 0; d < DKH; d++) {
            float a[8], bb[8];
            #pragma unroll
            for (int i = 0; i < 8; i++) a[i] = sm.Qs[ty * 8 + i][d];
            float4 b0 = *(const float4*)&sm.Kst[d][tx * 8];
            float4 b1 = *(const float4*)&sm.Kst[d][tx * 8 + 4];
            bb[0] = b0.x; bb[1] = b0.y; bb[2] = b0.z; bb[3] = b0.w;
            bb[4] = b1.x; bb[5] = b1.y; bb[6] = b1.z; bb[7] = b1.w;
            #pragma unroll
            for (int i = 0; i < 8; i++)
                #pragma unroll
                for (int j = 0; j < 8; j++)
                    sreg[i][j] = fmaf(a[i], bb[j], sreg[i][j]);
        }

        // Scale + mask (32-bit mask words; nonzero = keep).
        #pragma unroll
        for (int i = 0; i < 8; i++) {
            const int* Mrow = Mb + (size_t)(ty * 8 + i) * S + k0 + tx * 8;
            int4 m0 = *(const int4*)(Mrow);
            int4 m1 = *(const int4*)(Mrow + 4);
            int mv[8] = {m0.x, m0.y, m0.z, m0.w, m1.x, m1.y, m1.z, m1.w};
            #pragma unroll
            for (int j = 0; j < 8; j++) {
                float sv = sreg[i][j] * 0.125f;           // 1/sqrt(64)
                sreg[i][j] = (mv[j] != 0) ? sv : -1.0e9f;
            }
        }

        // Row max (partial per thread -> smem -> 128-thread reduce).
        #pragma unroll
        for (int i = 0; i < 8; i++) {
            float lm = sreg[i][0];
            #pragma unroll
            for (int j = 1; j < 8; j++) lm = fmaxf(lm, sreg[i][j]);
            sm.red[ty * 8 + i][tx] = lm;
        }
        __syncthreads();
        if (tid < 128) {
            float mold = sm.mrow[tid];
            float tm = sm.red[tid][0];
            #pragma unroll
            for (int j = 1; j < 16; j++) tm = fmaxf(tm, sm.red[tid][j]);
            float mn = fmaxf(mold, tm);
            sm.alph[tid] = __expf(mold - mn);
            sm.mrow[tid] = mn;
        }
        __syncthreads();

        // exp, partial row sums, stage P to smem.
        #pragma unroll
        for (int i = 0; i < 8; i++) {
            float mn = sm.mrow[ty * 8 + i];
            float ls = 0.f;
            #pragma unroll
            for (int j = 0; j < 8; j++) {
                float p = __expf(sreg[i][j] - mn);
                ls += p;
                sreg[i][j] = p;
            }
            sm.red[ty * 8 + i][tx] = ls;
            *(float4*)&sm.Ps[ty * 8 + i][tx * 8] =
                make_float4(sreg[i][0], sreg[i][1], sreg[i][2], sreg[i][3]);
            *(float4*)&sm.Ps[ty * 8 + i][tx * 8 + 4] =
                make_float4(sreg[i][4], sreg[i][5], sreg[i][6], sreg[i][7]);
        }
        __syncthreads();
        if (tid < 128) {
            float ls = 0.f;
            #pragma unroll
            for (int j = 0; j < 16; j++) ls += sm.red[tid][j];
            sm.lrow[tid] = sm.lrow[tid] * sm.alph[tid] + ls;
        }

        // Rescale accumulator, then O += P @ V (8x4 microtile over [128q x 64d]).
        #pragma unroll
        for (int i = 0; i < 8; i++) {
            float al = sm.alph[ty * 8 + i];
            #pragma unroll
            for (int j = 0; j < 4; j++) oacc[i][j] *= al;
        }
        #pragma unroll 4
        for (int k = 0; k < 128; k++) {
            float4 v = *(const float4*)&sm.Vs[k][tx * 4];
            #pragma unroll
            for (int i = 0; i < 8; i++) {
                float p = sm.Ps[ty * 8 + i][k];
                oacc[i][0] = fmaf(p, v.x, oacc[i][0]);
                oacc[i][1] = fmaf(p, v.y, oacc[i][1]);
                oacc[i][2] = fmaf(p, v.z, oacc[i][2]);
                oacc[i][3] = fmaf(p, v.w, oacc[i][3]);
            }
        }
        __syncthreads();
    }

    // Epilogue: divide by l and write merged-head layout [b, q, h*64 + d].
    float* Og = g_X + ((size_t)b * S + q0) * DMODEL + h * DKH;
    #pragma unroll
    for (int i = 0; i < 8; i++) {
        float inv = 1.f / sm.lrow[ty * 8 + i];
        *(float4*)(Og + (size_t)(ty * 8 + i) * DMODEL + tx * 4) =
            make_float4(oacc[i][0] * inv, oacc[i][1] * inv,
                        oacc[i][2] * inv, oacc[i][3] * inv);
    }
}

// ---------------------------------------------------------------------------
extern "C" void kernel_launch(void* const* d_in, const int* in_sizes, int n_in,
                              void* d_out, int out_size)
{
    const float* q  = (const float*)d_in[0];
    const float* k  = (const float*)d_in[1];
    const float* v  = (const float*)d_in[2];
    const int* mask = (const int*)d_in[3];
    const float* w_q = (const float*)d_in[4];
    const float* w_k = (const float*)d_in[5];
    const float* w_v = (const float*)d_in[6];
    const float* w_o = (const float*)d_in[7];
    float* out = (float*)d_out;

    const int M = in_sizes[0] / DMODEL;                       // B*S = 4096
    const int S = (int)(((long long)in_sizes[3]) / M);        // 2048
    const int B = M / S;                                      // 2

    float *gq, *gk, *gv, *gx;
    cudaGetSymbolAddress((void**)&gq, g_Q);
    cudaGetSymbolAddress((void**)&gk, g_K);
    cudaGetSymbolAddress((void**)&gv, g_V);
    cudaGetSymbolAddress((void**)&gx, g_X);

    dim3 gg(DMODEL / 128, M / 128);
    sgemm_nt_128<<<gg, 256>>>(q, w_q, gq, M, DMODEL, DMODEL);
    sgemm_nt_128<<<gg, 256>>>(k, w_k, gk, M, DMODEL, DMODEL);
    sgemm_nt_128<<<gg, 256>>>(v, w_v, gv, M, DMODEL, DMODEL);

    int smbytes = (int)sizeof(AttnSmem);
    cudaFuncSetAttribute(flash_attn_f32,
                         cudaFuncAttributeMaxDynamicSharedMemorySize, smbytes);
    dim3 ga(S / 128, NHEADS, B);
    flash_attn_f32<<<ga, 256, smbytes>>>(mask, S);

    sgemm_nt_128<<<gg, 256>>>(gx, w_o, out, M, DMODEL, DMODEL);
}

// round 5
// speedup vs baseline: 2.2216x; 2.2216x over previous
#include <cuda_runtime.h>
#include <cuda_bf16.h>
#include <cstdint>

#define DMODEL 1024
#define NHEADS 16
#define DKH    64

// Scratch (allocation-free rule: __device__ globals). 4 x 16 MB.
__device__ float g_Q[4096 * 1024];
__device__ float g_K[4096 * 1024];
__device__ float g_V[4096 * 1024];
__device__ float g_X[4096 * 1024];

// ===========================================================================
// mma.sync / ldmatrix helpers (generic PTX, works on compute_103)
// ===========================================================================
__device__ __forceinline__ uint32_t smem_u32(const void* p) {
    uint32_t a;
    asm("{ .reg .u64 t; cvta.to.shared.u64 t, %1; cvt.u32.u64 %0, t; }"
        : "=r"(a) : "l"(p));
    return a;
}

__device__ __forceinline__ void ldsm4(uint32_t* r, uint32_t a) {
    asm volatile("ldmatrix.sync.aligned.m8n8.x4.shared.b16 {%0,%1,%2,%3}, [%4];"
                 : "=r"(r[0]), "=r"(r[1]), "=r"(r[2]), "=r"(r[3]) : "r"(a));
}
__device__ __forceinline__ void ldsm4t(uint32_t* r, uint32_t a) {
    asm volatile("ldmatrix.sync.aligned.m8n8.x4.trans.shared.b16 {%0,%1,%2,%3}, [%4];"
                 : "=r"(r[0]), "=r"(r[1]), "=r"(r[2]), "=r"(r[3]) : "r"(a));
}

// D(16x8,f32) += A(16x16 bf16, row) * B(16x8 bf16, col)
__device__ __forceinline__ void mma_bf16(float* c, const uint32_t* a, const uint32_t* b) {
    asm volatile("mma.sync.aligned.m16n8k16.row.col.f32.bf16.bf16.f32 "
                 "{%0,%1,%2,%3}, {%4,%5,%6,%7}, {%8,%9}, {%0,%1,%2,%3};"
                 : "+f"(c[0]), "+f"(c[1]), "+f"(c[2]), "+f"(c[3])
                 : "r"(a[0]), "r"(a[1]), "r"(a[2]), "r"(a[3]),
                   "r"(b[0]), "r"(b[1]));
}

__device__ __forceinline__ uint32_t pack_bf16x2(float a, float b) {
    __nv_bfloat162 t = __floats2bfloat162_rn(a, b);
    return *reinterpret_cast<uint32_t*>(&t);
}

// Split float4 into bf16 hi (rounded) and lo (residual) packed pairs.
__device__ __forceinline__ void split4(float4 v, uint2& hi, uint2& lo) {
    float h0 = __bfloat162float(__float2bfloat16(v.x));
    float h1 = __bfloat162float(__float2bfloat16(v.y));
    float h2 = __bfloat162float(__float2bfloat16(v.z));
    float h3 = __bfloat162float(__float2bfloat16(v.w));
    hi = make_uint2(pack_bf16x2(h0, h1), pack_bf16x2(h2, h3));
    lo = make_uint2(pack_bf16x2(v.x - h0, v.y - h1), pack_bf16x2(v.z - h2, v.w - h3));
}

// ===========================================================================
// Tensor-core GEMM: C[M,N] = A[M,K] @ B[N,K]^T, fp32 in/out,
// 3-term bf16 split. 128x128 tile, BK=32, double-buffered SMEM, mma.sync.
// ===========================================================================
#define GSTRIDE 80                 // bytes per 32+8 bf16 row
#define GT_A_HI 0
#define GT_A_LO (128 * GSTRIDE)
#define GT_B_HI (2 * 128 * GSTRIDE)
#define GT_B_LO (3 * 128 * GSTRIDE)
#define GSTAGE  (4 * 128 * GSTRIDE)
#define GEMM_SMEM (2 * GSTAGE)

__global__ __launch_bounds__(256) void gemm_tc_nt(
    const float* __restrict__ A, const float* __restrict__ B,
    float* __restrict__ C, int M, int N, int K)
{
    extern __shared__ char smraw[];
    const uint32_t sb = smem_u32(smraw);
    const int tid = threadIdx.x, wid = tid >> 5, lane = tid & 31;
    const int wm = wid >> 1, wn = wid & 1;
    const int m0 = blockIdx.y * 128, n0 = blockIdx.x * 128;
    const int lr = lane & 7, lmat = lane >> 3;

    float acc[2][8][4];
    #pragma unroll
    for (int i = 0; i < 2; i++)
        #pragma unroll
        for (int j = 0; j < 8; j++)
            #pragma unroll
            for (int t = 0; t < 4; t++) acc[i][j][t] = 0.f;

    const int NC = K / 32;

    // prologue: chunk 0 -> stage 0
    {
        #pragma unroll
        for (int s = 0; s < 4; s++) {
            int f = tid + s * 256;
            int row = f >> 3, col = (f & 7) * 4;
            float4 av = *(const float4*)(A + (size_t)(m0 + row) * K + col);
            float4 bv = *(const float4*)(B + (size_t)(n0 + row) * K + col);
            uint32_t off = (uint32_t)row * GSTRIDE + col * 2;
            uint2 hi, lo;
            split4(av, hi, lo);
            *(uint2*)(smraw + GT_A_HI + off) = hi;
            *(uint2*)(smraw + GT_A_LO + off) = lo;
            split4(bv, hi, lo);
            *(uint2*)(smraw + GT_B_HI + off) = hi;
            *(uint2*)(smraw + GT_B_LO + off) = lo;
        }
    }
    __syncthreads();

    for (int i = 0; i < NC; i++) {
        const int st = i & 1;
        const uint32_t stb = sb + st * GSTAGE;

        float4 av[4], bv[4];
        if (i + 1 < NC) {
            int kc = (i + 1) * 32;
            #pragma unroll
            for (int s = 0; s < 4; s++) {
                int f = tid + s * 256;
                int row = f >> 3, col = (f & 7) * 4;
                av[s] = *(const float4*)(A + (size_t)(m0 + row) * K + kc + col);
                bv[s] = *(const float4*)(B + (size_t)(n0 + row) * K + kc + col);
            }
        }

        // MMA over this stage: 2 k-steps of 16
        #pragma unroll
        for (int ks = 0; ks < 2; ks++) {
            uint32_t ah[2][4], al[2][4];
            #pragma unroll
            for (int mi = 0; mi < 2; mi++) {
                uint32_t ra = stb + GT_A_HI
                    + (uint32_t)(wm * 32 + mi * 16 + lr + (lmat & 1) * 8) * GSTRIDE
                    + (ks * 16 + (lmat >> 1) * 8) * 2;
                ldsm4(ah[mi], ra);
                ldsm4(al[mi], ra + (GT_A_LO - GT_A_HI));
            }
            uint32_t bh[8][2], bl[8][2];
            #pragma unroll
            for (int p = 0; p < 4; p++) {
                uint32_t rb = stb + GT_B_HI
                    + (uint32_t)(wn * 64 + p * 16 + (lmat >> 1) * 8 + lr) * GSTRIDE
                    + (ks * 16 + (lmat & 1) * 8) * 2;
                uint32_t t[4];
                ldsm4(t, rb);
                bh[2 * p][0] = t[0]; bh[2 * p][1] = t[1];
                bh[2 * p + 1][0] = t[2]; bh[2 * p + 1][1] = t[3];
                ldsm4(t, rb + (GT_B_LO - GT_B_HI));
                bl[2 * p][0] = t[0]; bl[2 * p][1] = t[1];
                bl[2 * p + 1][0] = t[2]; bl[2 * p + 1][1] = t[3];
            }
            #pragma unroll
            for (int mi = 0; mi < 2; mi++)
                #pragma unroll
                for (int nj = 0; nj < 8; nj++) {
                    mma_bf16(acc[mi][nj], ah[mi], bh[nj]);
                    mma_bf16(acc[mi][nj], ah[mi], bl[nj]);
                    mma_bf16(acc[mi][nj], al[mi], bh[nj]);
                }
        }
        __syncthreads();

        if (i + 1 < NC) {
            char* stg = smraw + ((i + 1) & 1) * GSTAGE;
            #pragma unroll
            for (int s = 0; s < 4; s++) {
                int f = tid + s * 256;
                int row = f >> 3, col = (f & 7) * 4;
                uint32_t off = (uint32_t)row * GSTRIDE + col * 2;
                uint2 hi, lo;
                split4(av[s], hi, lo);
                *(uint2*)(stg + GT_A_HI + off) = hi;
                *(uint2*)(stg + GT_A_LO + off) = lo;
                split4(bv[s], hi, lo);
                *(uint2*)(stg + GT_B_HI + off) = hi;
                *(uint2*)(stg + GT_B_LO + off) = lo;
            }
            __syncthreads();
        }
    }

    // epilogue
    #pragma unroll
    for (int mi = 0; mi < 2; mi++) {
        int r0 = m0 + wm * 32 + mi * 16 + (lane >> 2);
        #pragma unroll
        for (int nj = 0; nj < 8; nj++) {
            int col = n0 + wn * 64 + nj * 8 + (lane & 3) * 2;
            *(float2*)(C + (size_t)r0 * N + col) =
                make_float2(acc[mi][nj][0], acc[mi][nj][1]);
            *(float2*)(C + (size_t)(r0 + 8) * N + col) =
                make_float2(acc[mi][nj][2], acc[mi][nj][3]);
        }
    }
}

// ===========================================================================
// Flash attention with mma.sync: 128-query tile per CTA, 64-key tiles.
// QK^T and PV both tensor-core bf16 3-term; softmax staged via SMEM.
// ===========================================================================
#define AQ_HI 0
#define AQ_LO 18432
#define AK_HI 36864
#define AK_LO 46080
#define AV_HI 55296
#define AV_LO 64512
#define A_SS  73728          // fp32 scores [128][68]
#define AP_HI 108544
#define AP_LO 126976
#define A_RED 145408         // [128][8] f32
#define A_MRO 149504
#define A_LRO 150016
#define A_ALP 150528
#define ATTN_SMEM 151040
#define QSTR 144             // 72 bf16 per row
#define SSTR 68              // fp32 scores row stride (elements)

__global__ __launch_bounds__(256) void flash_attn_tc(
    const int* __restrict__ mask, int S)
{
    extern __shared__ char smraw[];
    const uint32_t sb = smem_u32(smraw);
    float* Sf   = (float*)(smraw + A_SS);
    float* red  = (float*)(smraw + A_RED);
    float* mrow = (float*)(smraw + A_MRO);
    float* lrow = (float*)(smraw + A_LRO);
    float* alph = (float*)(smraw + A_ALP);

    const int tid = threadIdx.x, wid = tid >> 5, lane = tid & 31;
    const int lr = lane & 7, lmat = lane >> 3;
    const int b = blockIdx.z, h = blockIdx.y;
    const int q0 = blockIdx.x * 128;
    const int wq = wid >> 1;        // 0..3, 32 q rows
    const int wk = wid & 1;         // 0..1, 32 keys (QK) / 32 dims (PV)

    // Load + split Q tile [128 x 64]
    const float* Qg = g_Q + ((size_t)b * S + q0) * DMODEL + h * DKH;
    #pragma unroll
    for (int s = 0; s < 8; s++) {
        int f = tid + s * 256;
        int row = f >> 4, col = (f & 15) * 4;
        float4 v = *(const float4*)(Qg + (size_t)row * DMODEL + col);
        uint32_t off = (uint32_t)row * QSTR + col * 2;
        uint2 hi, lo;
        split4(v, hi, lo);
        *(uint2*)(smraw + AQ_HI + off) = hi;
        *(uint2*)(smraw + AQ_LO + off) = lo;
    }
    if (tid < 128) { mrow[tid] = -3.0e38f; lrow[tid] = 0.f; }

    float oacc[2][4][4];
    #pragma unroll
    for (int i = 0; i < 2; i++)
        #pragma unroll
        for (int j = 0; j < 4; j++)
            #pragma unroll
            for (int t = 0; t < 4; t++) oacc[i][j][t] = 0.f;

    // softmax scalar mapping: 4 rows x 8 cols per thread
    const int sty = tid >> 3;       // 0..31 -> rows sty*4..+3
    const int stx = tid & 7;        // col block of 8
    __syncthreads();

    for (int k0 = 0; k0 < S; k0 += 64) {
        // --- load + split K,V tiles [64 x 64] ---
        const float* Kg = g_K + ((size_t)b * S + k0) * DMODEL + h * DKH;
        const float* Vg = g_V + ((size_t)b * S + k0) * DMODEL + h * DKH;
        #pragma unroll
        for (int s = 0; s < 4; s++) {
            int f = tid + s * 256;
            int row = f >> 4, col = (f & 15) * 4;
            uint32_t off = (uint32_t)row * QSTR + col * 2;
            uint2 hi, lo;
            float4 kv = *(const float4*)(Kg + (size_t)row * DMODEL + col);
            split4(kv, hi, lo);
            *(uint2*)(smraw + AK_HI + off) = hi;
            *(uint2*)(smraw + AK_LO + off) = lo;
            float4 vv = *(const float4*)(Vg + (size_t)row * DMODEL + col);
            split4(vv, hi, lo);
            *(uint2*)(smraw + AV_HI + off) = hi;
            *(uint2*)(smraw + AV_LO + off) = lo;
        }
        __syncthreads();

        // --- QK^T: warp tile 32q x 32k, K-dim 64 (4 k-steps) ---
        {
            float sacc[2][4][4];
            #pragma unroll
            for (int i = 0; i < 2; i++)
                #pragma unroll
                for (int j = 0; j < 4; j++)
                    #pragma unroll
                    for (int t = 0; t < 4; t++) sacc[i][j][t] = 0.f;

            #pragma unroll
            for (int ks = 0; ks < 4; ks++) {
                uint32_t qh[2][4], ql[2][4];
                #pragma unroll
                for (int mi = 0; mi < 2; mi++) {
                    uint32_t ra = sb + AQ_HI
                        + (uint32_t)(wq * 32 + mi * 16 + lr + (lmat & 1) * 8) * QSTR
                        + (ks * 16 + (lmat >> 1) * 8) * 2;
                    ldsm4(qh[mi], ra);
                    ldsm4(ql[mi], ra + (AQ_LO - AQ_HI));
                }
                uint32_t kh[4][2], kl[4][2];
                #pragma unroll
                for (int p = 0; p < 2; p++) {
                    uint32_t rb = sb + AK_HI
                        + (uint32_t)(wk * 32 + p * 16 + (lmat >> 1) * 8 + lr) * QSTR
                        + (ks * 16 + (lmat & 1) * 8) * 2;
                    uint32_t t[4];
                    ldsm4(t, rb);
                    kh[2 * p][0] = t[0]; kh[2 * p][1] = t[1];
                    kh[2 * p + 1][0] = t[2]; kh[2 * p + 1][1] = t[3];
                    ldsm4(t, rb + (AK_LO - AK_HI));
                    kl[2 * p][0] = t[0]; kl[2 * p][1] = t[1];
                    kl[2 * p + 1][0] = t[2]; kl[2 * p + 1][1] = t[3];
                }
                #pragma unroll
                for (int mi = 0; mi < 2; mi++)
                    #pragma unroll
                    for (int nj = 0; nj < 4; nj++) {
                        mma_bf16(sacc[mi][nj], qh[mi], kh[nj]);
                        mma_bf16(sacc[mi][nj], qh[mi], kl[nj]);
                        mma_bf16(sacc[mi][nj], ql[mi], kh[nj]);
                    }
            }
            // scores -> SMEM
            #pragma unroll
            for (int mi = 0; mi < 2; mi++) {
                int r0 = wq * 32 + mi * 16 + (lane >> 2);
                #pragma unroll
                for (int nj = 0; nj < 4; nj++) {
                    int col = wk * 32 + nj * 8 + (lane & 3) * 2;
                    *(float2*)(Sf + (size_t)r0 * SSTR + col) =
                        make_float2(sacc[mi][nj][0], sacc[mi][nj][1]);
                    *(float2*)(Sf + (size_t)(r0 + 8) * SSTR + col) =
                        make_float2(sacc[mi][nj][2], sacc[mi][nj][3]);
                }
            }
        }
        __syncthreads();

        // --- phase1: scale + mask + row max ---
        #pragma unroll
        for (int rr = 0; rr < 4; rr++) {
            int row = sty * 4 + rr;
            float* sp = Sf + (size_t)row * SSTR + stx * 8;
            const int* mp = mask + ((size_t)b * S + q0 + row) * S + k0 + stx * 8;
            int4 m0v = *(const int4*)(mp);
            int4 m1v = *(const int4*)(mp + 4);
            int mv[8] = {m0v.x, m0v.y, m0v.z, m0v.w, m1v.x, m1v.y, m1v.z, m1v.w};
            float sv[8];
            *(float4*)&sv[0] = *(const float4*)(sp);
            *(float4*)&sv[4] = *(const float4*)(sp + 4);
            float lm = -3.0e38f;
            #pragma unroll
            for (int j = 0; j < 8; j++) {
                sv[j] = (mv[j] != 0) ? sv[j] * 0.125f : -1.0e9f;
                lm = fmaxf(lm, sv[j]);
            }
            *(float4*)(sp)     = *(float4*)&sv[0];
            *(float4*)(sp + 4) = *(float4*)&sv[4];
            if (rr == 0) red[(size_t)row * 8 + stx] = lm;
            else red[(size_t)row * 8 + stx] = lm;
        }
        __syncthreads();
        if (tid < 128) {
            float mold = mrow[tid];
            float tm = red[(size_t)tid * 8];
            #pragma unroll
            for (int j = 1; j < 8; j++) tm = fmaxf(tm, red[(size_t)tid * 8 + j]);
            float mn = fmaxf(mold, tm);
            alph[tid] = __expf(mold - mn);
            mrow[tid] = mn;
        }
        __syncthreads();

        // --- phase2: exp, row sums, P hi/lo to SMEM ---
        #pragma unroll
        for (int rr = 0; rr < 4; rr++) {
            int row = sty * 4 + rr;
            float mn = mrow[row];
            float* sp = Sf + (size_t)row * SSTR + stx * 8;
            float sv[8];
            *(float4*)&sv[0] = *(const float4*)(sp);
            *(float4*)&sv[4] = *(const float4*)(sp + 4);
            float ls = 0.f;
            #pragma unroll
            for (int j = 0; j < 8; j++) {
                sv[j] = __expf(sv[j] - mn);
                ls += sv[j];
            }
            uint32_t off = (uint32_t)row * QSTR + stx * 16;
            uint2 hi, lo;
            split4(make_float4(sv[0], sv[1], sv[2], sv[3]), hi, lo);
            *(uint2*)(smraw + AP_HI + off) = hi;
            *(uint2*)(smraw + AP_LO + off) = lo;
            split4(make_float4(sv[4], sv[5], sv[6], sv[7]), hi, lo);
            *(uint2*)(smraw + AP_HI + off + 8) = hi;
            *(uint2*)(smraw + AP_LO + off + 8) = lo;
            red[(size_t)row * 8 + stx] = ls;
        }
        __syncthreads();
        if (tid < 128) {
            float ls = 0.f;
            #pragma unroll
            for (int j = 0; j < 8; j++) ls += red[(size_t)tid * 8 + j];
            lrow[tid] = lrow[tid] * alph[tid] + ls;
        }

        // --- PV: warp tile 32q x 32d, K-dim 64 keys ---
        {
            // rescale O by alpha
            #pragma unroll
            for (int mi = 0; mi < 2; mi++) {
                float a0 = alph[wq * 32 + mi * 16 + (lane >> 2)];
                float a1 = alph[wq * 32 + mi * 16 + (lane >> 2) + 8];
                #pragma unroll
                for (int nj = 0; nj < 4; nj++) {
                    oacc[mi][nj][0] *= a0; oacc[mi][nj][1] *= a0;
                    oacc[mi][nj][2] *= a1; oacc[mi][nj][3] *= a1;
                }
            }
            #pragma unroll
            for (int ks = 0; ks < 4; ks++) {
                uint32_t ph[2][4], pl[2][4];
                #pragma unroll
                for (int mi = 0; mi < 2; mi++) {
                    uint32_t ra = sb + AP_HI
                        + (uint32_t)(wq * 32 + mi * 16 + lr + (lmat & 1) * 8) * QSTR
                        + (ks * 16 + (lmat >> 1) * 8) * 2;
                    ldsm4(ph[mi], ra);
                    ldsm4(pl[mi], ra + (AP_LO - AP_HI));
                }
                uint32_t vh[4][2], vl[4][2];
                #pragma unroll
                for (int p = 0; p < 2; p++) {
                    // trans load: V is [key][d]; B needs [d][key]
                    uint32_t rb = sb + AV_HI
                        + (uint32_t)(ks * 16 + (lmat & 1) * 8 + lr) * QSTR
                        + (wk * 32 + p * 16 + (lmat >> 1) * 8) * 2;
                    uint32_t t[4];
                    ldsm4t(t, rb);
                    vh[2 * p][0] = t[0]; vh[2 * p][1] = t[1];
                    vh[2 * p + 1][0] = t[2]; vh[2 * p + 1][1] = t[3];
                    ldsm4t(t, rb + (AV_LO - AV_HI));
                    vl[2 * p][0] = t[0]; vl[2 * p][1] = t[1];
                    vl[2 * p + 1][0] = t[2]; vl[2 * p + 1][1] = t[3];
                }
                #pragma unroll
                for (int mi = 0; mi < 2; mi++)
                    #pragma unroll
                    for (int nj = 0; nj < 4; nj++) {
                        mma_bf16(oacc[mi][nj], ph[mi], vh[nj]);
                        mma_bf16(oacc[mi][nj], ph[mi], vl[nj]);
                        mma_bf16(oacc[mi][nj], pl[mi], vh[nj]);
                    }
            }
        }
        __syncthreads();
    }

    // --- epilogue: O / l, write merged-head layout ---
    float* Og = g_X + ((size_t)b * S + q0) * DMODEL + h * DKH;
    #pragma unroll
    for (int mi = 0; mi < 2; mi++) {
        int r0 = wq * 32 + mi * 16 + (lane >> 2);
        float i0 = 1.f / lrow[r0];
        float i1 = 1.f / lrow[r0 + 8];
        #pragma unroll
        for (int nj = 0; nj < 4; nj++) {
            int col = wk * 32 + nj * 8 + (lane & 3) * 2;
            *(float2*)(Og + (size_t)r0 * DMODEL + col) =
                make_float2(oacc[mi][nj][0] * i0, oacc[mi][nj][1] * i0);
            *(float2*)(Og + (size_t)(r0 + 8) * DMODEL + col) =
                make_float2(oacc[mi][nj][2] * i1, oacc[mi][nj][3] * i1);
        }
    }
}

// ---------------------------------------------------------------------------
extern "C" void kernel_launch(void* const* d_in, const int* in_sizes, int n_in,
                              void* d_out, int out_size)
{
    const float* q  = (const float*)d_in[0];
    const float* k  = (const float*)d_in[1];
    const float* v  = (const float*)d_in[2];
    const int* mask = (const int*)d_in[3];
    const float* w_q = (const float*)d_in[4];
    const float* w_k = (const float*)d_in[5];
    const float* w_v = (const float*)d_in[6];
    const float* w_o = (const float*)d_in[7];
    float* out = (float*)d_out;

    const int M = in_sizes[0] / DMODEL;                       // B*S = 4096
    const int S = (int)(((long long)in_sizes[3]) / M);        // 2048
    const int B = M / S;                                      // 2

    float *gq, *gk, *gv, *gx;
    cudaGetSymbolAddress((void**)&gq, g_Q);
    cudaGetSymbolAddress((void**)&gk, g_K);
    cudaGetSymbolAddress((void**)&gv, g_V);
    cudaGetSymbolAddress((void**)&gx, g_X);

    cudaFuncSetAttribute(gemm_tc_nt,
                         cudaFuncAttributeMaxDynamicSharedMemorySize, GEMM_SMEM);
    cudaFuncSetAttribute(flash_attn_tc,
                         cudaFuncAttributeMaxDynamicSharedMemorySize, ATTN_SMEM);

    dim3 gg(DMODEL / 128, M / 128);
    gemm_tc_nt<<<gg, 256, GEMM_SMEM>>>(q, w_q, gq, M, DMODEL, DMODEL);
    gemm_tc_nt<<<gg, 256, GEMM_SMEM>>>(k, w_k, gk, M, DMODEL, DMODEL);
    gemm_tc_nt<<<gg, 256, GEMM_SMEM>>>(v, w_v, gv, M, DMODEL, DMODEL);

    dim3 ga(S / 128, NHEADS, B);
    flash_attn_tc<<<ga, 256, ATTN_SMEM>>>(mask, S);

    gemm_tc_nt<<<gg, 256, GEMM_SMEM>>>(gx, w_o, out, M, DMODEL, DMODEL);
}

// round 7
// speedup vs baseline: 2.9286x; 1.3183x over previous
#include <cuda_runtime.h>
#include <cuda_bf16.h>
#include <cstdint>

#define DMODEL 1024
#define NHEADS 16
#define DKH    64

// Scratch (__device__ globals per allocation rules).
__device__ float g_X[4096 * 1024];                              // attn out (fp32)
__device__ __nv_bfloat16 g_Qh[4096 * 1024], g_Ql[4096 * 1024];  // pre-split QKV
__device__ __nv_bfloat16 g_Kh[4096 * 1024], g_Kl[4096 * 1024];
__device__ __nv_bfloat16 g_Vh[4096 * 1024], g_Vl[4096 * 1024];

// ===========================================================================
// helpers (generic PTX, compute_103-safe)
// ===========================================================================
__device__ __forceinline__ uint32_t smem_u32(const void* p) {
    uint32_t a;
    asm("{ .reg .u64 t; cvta.to.shared.u64 t, %1; cvt.u32.u64 %0, t; }"
        : "=r"(a) : "l"(p));
    return a;
}
__device__ __forceinline__ void ldsm4(uint32_t* r, uint32_t a) {
    asm volatile("ldmatrix.sync.aligned.m8n8.x4.shared.b16 {%0,%1,%2,%3}, [%4];"
                 : "=r"(r[0]), "=r"(r[1]), "=r"(r[2]), "=r"(r[3]) : "r"(a));
}
__device__ __forceinline__ void ldsm4t(uint32_t* r, uint32_t a) {
    asm volatile("ldmatrix.sync.aligned.m8n8.x4.trans.shared.b16 {%0,%1,%2,%3}, [%4];"
                 : "=r"(r[0]), "=r"(r[1]), "=r"(r[2]), "=r"(r[3]) : "r"(a));
}
__device__ __forceinline__ void mma_bf16(float* c, const uint32_t* a, const uint32_t* b) {
    asm volatile("mma.sync.aligned.m16n8k16.row.col.f32.bf16.bf16.f32 "
                 "{%0,%1,%2,%3}, {%4,%5,%6,%7}, {%8,%9}, {%0,%1,%2,%3};"
                 : "+f"(c[0]), "+f"(c[1]), "+f"(c[2]), "+f"(c[3])
                 : "r"(a[0]), "r"(a[1]), "r"(a[2]), "r"(a[3]),
                   "r"(b[0]), "r"(b[1]));
}
__device__ __forceinline__ uint32_t pack_bf16x2(float a, float b) {
    __nv_bfloat162 t = __floats2bfloat162_rn(a, b);
    return *reinterpret_cast<uint32_t*>(&t);
}
__device__ __forceinline__ void split4(float4 v, uint2& hi, uint2& lo) {
    float h0 = __bfloat162float(__float2bfloat16(v.x));
    float h1 = __bfloat162float(__float2bfloat16(v.y));
    float h2 = __bfloat162float(__float2bfloat16(v.z));
    float h3 = __bfloat162float(__float2bfloat16(v.w));
    hi = make_uint2(pack_bf16x2(h0, h1), pack_bf16x2(h2, h3));
    lo = make_uint2(pack_bf16x2(v.x - h0, v.y - h1), pack_bf16x2(v.z - h2, v.w - h3));
}
__device__ __forceinline__ float ex2f(float x) {
    float y;
    asm("ex2.approx.f32 %0, %1;" : "=f"(y) : "f"(x));
    return y;
}
__device__ __forceinline__ float bf16rnd(float x) {
    return __bfloat162float(__float2bfloat16(x));
}
__device__ __forceinline__ void cp16(uint32_t dst, const void* src) {
    asm volatile("cp.async.cg.shared.global [%0], [%1], 16;" :: "r"(dst), "l"(src));
}
#define CP_COMMIT() asm volatile("cp.async.commit_group;" ::: "memory")
#define CP_WAIT1()  asm volatile("cp.async.wait_group 1;" ::: "memory")
#define CP_WAIT0()  asm volatile("cp.async.wait_group 0;" ::: "memory")

// ===========================================================================
// GEMM: C = A[M,K] @ B[N,K]^T * scale; output fp32 OR pre-split bf16 hi/lo.
// 128x128 tile, BK=32, double-buffered SMEM, mma.sync 3-term bf16 split.
// ===========================================================================
#define GSTRIDE 80
#define GT_A_HI 0
#define GT_A_LO (128 * GSTRIDE)
#define GT_B_HI (2 * 128 * GSTRIDE)
#define GT_B_LO (3 * 128 * GSTRIDE)
#define GSTAGE  (4 * 128 * GSTRIDE)
#define GEMM_SMEM (2 * GSTAGE)

__global__ __launch_bounds__(256) void gemm_tc_nt(
    const float* __restrict__ A, const float* __restrict__ B,
    float* __restrict__ C, __nv_bfloat16* __restrict__ Chi,
    __nv_bfloat16* __restrict__ Clo,
    int M, int N, int K, float scale)
{
    extern __shared__ char smraw[];
    const uint32_t sb = smem_u32(smraw);
    const int tid = threadIdx.x, wid = tid >> 5, lane = tid & 31;
    const int wm = wid >> 1, wn = wid & 1;
    const int m0 = blockIdx.y * 128, n0 = blockIdx.x * 128;
    const int lr = lane & 7, lmat = lane >> 3;

    float acc[2][8][4];
    #pragma unroll
    for (int i = 0; i < 2; i++)
        #pragma unroll
        for (int j = 0; j < 8; j++)
            #pragma unroll
            for (int t = 0; t < 4; t++) acc[i][j][t] = 0.f;

    const int NC = K / 32;

    {
        #pragma unroll
        for (int s = 0; s < 4; s++) {
            int f = tid + s * 256;
            int row = f >> 3, col = (f & 7) * 4;
            float4 av = *(const float4*)(A + (size_t)(m0 + row) * K + col);
            float4 bv = *(const float4*)(B + (size_t)(n0 + row) * K + col);
            uint32_t off = (uint32_t)row * GSTRIDE + col * 2;
            uint2 hi, lo;
            split4(av, hi, lo);
            *(uint2*)(smraw + GT_A_HI + off) = hi;
            *(uint2*)(smraw + GT_A_LO + off) = lo;
            split4(bv, hi, lo);
            *(uint2*)(smraw + GT_B_HI + off) = hi;
            *(uint2*)(smraw + GT_B_LO + off) = lo;
        }
    }
    __syncthreads();

    for (int i = 0; i < NC; i++) {
        const uint32_t stb = sb + (i & 1) * GSTAGE;

        float4 av[4], bv[4];
        if (i + 1 < NC) {
            int kc = (i + 1) * 32;
            #pragma unroll
            for (int s = 0; s < 4; s++) {
                int f = tid + s * 256;
                int row = f >> 3, col = (f & 7) * 4;
                av[s] = *(const float4*)(A + (size_t)(m0 + row) * K + kc + col);
                bv[s] = *(const float4*)(B + (size_t)(n0 + row) * K + kc + col);
            }
        }

        #pragma unroll
        for (int ks = 0; ks < 2; ks++) {
            uint32_t ah[2][4], al[2][4];
            #pragma unroll
            for (int mi = 0; mi < 2; mi++) {
                uint32_t ra = stb + GT_A_HI
                    + (uint32_t)(wm * 32 + mi * 16 + lr + (lmat & 1) * 8) * GSTRIDE
                    + (ks * 16 + (lmat >> 1) * 8) * 2;
                ldsm4(ah[mi], ra);
                ldsm4(al[mi], ra + (GT_A_LO - GT_A_HI));
            }
            #pragma unroll
            for (int p = 0; p < 4; p++) {
                uint32_t rb = stb + GT_B_HI
                    + (uint32_t)(wn * 64 + p * 16 + (lmat >> 1) * 8 + lr) * GSTRIDE
                    + (ks * 16 + (lmat & 1) * 8) * 2;
                uint32_t t[4], u[4];
                ldsm4(t, rb);
                ldsm4(u, rb + (GT_B_LO - GT_B_HI));
                #pragma unroll
                for (int mi = 0; mi < 2; mi++) {
                    mma_bf16(acc[mi][2 * p],     ah[mi], t + 0);
                    mma_bf16(acc[mi][2 * p],     ah[mi], u + 0);
                    mma_bf16(acc[mi][2 * p],     al[mi], t + 0);
                    mma_bf16(acc[mi][2 * p + 1], ah[mi], t + 2);
                    mma_bf16(acc[mi][2 * p + 1], ah[mi], u + 2);
                    mma_bf16(acc[mi][2 * p + 1], al[mi], t + 2);
                }
            }
        }
        __syncthreads();

        if (i + 1 < NC) {
            char* stg = smraw + ((i + 1) & 1) * GSTAGE;
            #pragma unroll
            for (int s = 0; s < 4; s++) {
                int f = tid + s * 256;
                int row = f >> 3, col = (f & 7) * 4;
                uint32_t off = (uint32_t)row * GSTRIDE + col * 2;
                uint2 hi, lo;
                split4(av[s], hi, lo);
                *(uint2*)(stg + GT_A_HI + off) = hi;
                *(uint2*)(stg + GT_A_LO + off) = lo;
                split4(bv[s], hi, lo);
                *(uint2*)(stg + GT_B_HI + off) = hi;
                *(uint2*)(stg + GT_B_LO + off) = lo;
            }
            __syncthreads();
        }
    }

    // epilogue
    #pragma unroll
    for (int mi = 0; mi < 2; mi++) {
        int r0 = m0 + wm * 32 + mi * 16 + (lane >> 2);
        #pragma unroll
        for (int nj = 0; nj < 8; nj++) {
            int col = n0 + wn * 64 + nj * 8 + (lane & 3) * 2;
            float c0 = acc[mi][nj][0] * scale, c1 = acc[mi][nj][1] * scale;
            float c2 = acc[mi][nj][2] * scale, c3 = acc[mi][nj][3] * scale;
            if (Chi) {
                float h0 = bf16rnd(c0), h1 = bf16rnd(c1);
                float h2 = bf16rnd(c2), h3 = bf16rnd(c3);
                *(uint32_t*)(Chi + (size_t)r0 * N + col)       = pack_bf16x2(h0, h1);
                *(uint32_t*)(Clo + (size_t)r0 * N + col)       = pack_bf16x2(c0 - h0, c1 - h1);
                *(uint32_t*)(Chi + (size_t)(r0 + 8) * N + col) = pack_bf16x2(h2, h3);
                *(uint32_t*)(Clo + (size_t)(r0 + 8) * N + col) = pack_bf16x2(c2 - h2, c3 - h3);
            } else {
                *(float2*)(C + (size_t)r0 * N + col)       = make_float2(c0, c1);
                *(float2*)(C + (size_t)(r0 + 8) * N + col) = make_float2(c2, c3);
            }
        }
    }
}

// ===========================================================================
// Flash attention, FA2-style: warp owns 16 q rows; register softmax;
// cp.async double-buffered K/V (pre-split bf16); Q pre-scaled by 0.125*log2e.
// ===========================================================================
#define QSTR 144
#define AQ_HI 0
#define AQ_LO 18432
#define ABUF0 36864
#define ABUFSZ 73728          // Khi,Klo,Vhi,Vlo each 18432
#define ATTN_SMEM (ABUF0 + 2 * ABUFSZ)

__global__ __launch_bounds__(256) void flash_attn_tc(
    const int* __restrict__ mask, int S)
{
    extern __shared__ char smraw[];
    const uint32_t sb = smem_u32(smraw);
    const int tid = threadIdx.x, wid = tid >> 5, lane = tid & 31;
    const int lr = lane & 7, lmat = lane >> 3;
    const int b = blockIdx.z, h = blockIdx.y;
    const int q0 = blockIdx.x * 128;
    const int qrow = wid * 16;

    const size_t rowbase = (size_t)b * S;
    const __nv_bfloat16* Qhp = g_Qh + (rowbase + q0) * DMODEL + h * DKH;
    const __nv_bfloat16* Qlp = g_Ql + (rowbase + q0) * DMODEL + h * DKH;

    // --- issue Q (async): 2 arrays x 1024 16B-chunks ---
    #pragma unroll
    for (int s = 0; s < 4; s++) {
        int c = tid + s * 256;
        int row = c >> 3, off = c & 7;
        cp16(sb + AQ_HI + row * QSTR + off * 16, Qhp + (size_t)row * DMODEL + off * 8);
        cp16(sb + AQ_LO + row * QSTR + off * 16, Qlp + (size_t)row * DMODEL + off * 8);
    }
    // --- issue K/V tile 0 ---
    {
        const __nv_bfloat16* srcs[4] = {
            g_Kh + rowbase * DMODEL + h * DKH, g_Kl + rowbase * DMODEL + h * DKH,
            g_Vh + rowbase * DMODEL + h * DKH, g_Vl + rowbase * DMODEL + h * DKH };
        #pragma unroll
        for (int s = 0; s < 16; s++) {
            int c = tid + s * 256;
            int arr = c >> 10, cc = c & 1023;
            int row = cc >> 3, off = cc & 7;
            cp16(sb + ABUF0 + arr * 18432 + row * QSTR + off * 16,
                 srcs[arr] + (size_t)row * DMODEL + off * 8);
        }
    }
    CP_COMMIT();

    float oacc[8][4];
    #pragma unroll
    for (int j = 0; j < 8; j++)
        #pragma unroll
        for (int t = 0; t < 4; t++) oacc[j][t] = 0.f;
    float mrow0 = -3.0e38f, mrow1 = -3.0e38f, lrow0 = 0.f, lrow1 = 0.f;

    const int r0g = q0 + qrow + (lane >> 2);
    const int* mbase = mask + ((size_t)b * S + r0g) * S;

    const int NT = S / 128;
    for (int it = 0; it < NT; it++) {
        if (it + 1 < NT) {
            const int k1 = (it + 1) * 128;
            const uint32_t dst = sb + ABUF0 + ((it + 1) & 1) * ABUFSZ;
            const __nv_bfloat16* srcs[4] = {
                g_Kh + (rowbase + k1) * DMODEL + h * DKH,
                g_Kl + (rowbase + k1) * DMODEL + h * DKH,
                g_Vh + (rowbase + k1) * DMODEL + h * DKH,
                g_Vl + (rowbase + k1) * DMODEL + h * DKH };
            #pragma unroll
            for (int s = 0; s < 16; s++) {
                int c = tid + s * 256;
                int arr = c >> 10, cc = c & 1023;
                int row = cc >> 3, off = cc & 7;
                cp16(dst + arr * 18432 + row * QSTR + off * 16,
                     srcs[arr] + (size_t)row * DMODEL + off * 8);
            }
            CP_COMMIT();
            CP_WAIT1();
        } else {
            CP_WAIT0();
        }
        __syncthreads();

        const uint32_t kb = sb + ABUF0 + (it & 1) * ABUFSZ;
        const uint32_t vb = kb + 36864;
        const int k0 = it * 128;

        #pragma unroll
        for (int half = 0; half < 2; half++) {
            float sacc[8][4];
            #pragma unroll
            for (int j = 0; j < 8; j++)
                #pragma unroll
                for (int t = 0; t < 4; t++) sacc[j][t] = 0.f;

            // --- QK^T: 16q x 64k, d=64 ---
            #pragma unroll
            for (int ks = 0; ks < 4; ks++) {
                uint32_t qh[4], ql[4];
                uint32_t ra = sb + AQ_HI
                    + (uint32_t)(qrow + lr + (lmat & 1) * 8) * QSTR
                    + (ks * 16 + (lmat >> 1) * 8) * 2;
                ldsm4(qh, ra);
                ldsm4(ql, ra + (AQ_LO - AQ_HI));
                #pragma unroll
                for (int p = 0; p < 4; p++) {
                    uint32_t rb = kb
                        + (uint32_t)(half * 64 + p * 16 + (lmat >> 1) * 8 + lr) * QSTR
                        + (ks * 16 + (lmat & 1) * 8) * 2;
                    uint32_t t[4], u[4];
                    ldsm4(t, rb);
                    ldsm4(u, rb + 18432);
                    mma_bf16(sacc[2 * p],     qh, t + 0);
                    mma_bf16(sacc[2 * p],     qh, u + 0);
                    mma_bf16(sacc[2 * p],     ql, t + 0);
                    mma_bf16(sacc[2 * p + 1], qh, t + 2);
                    mma_bf16(sacc[2 * p + 1], qh, u + 2);
                    mma_bf16(sacc[2 * p + 1], ql, t + 2);
                }
            }

            // --- mask + row max (scores already in log2 domain) ---
            const int cb = k0 + half * 64 + (lane & 3) * 2;
            float tmax0 = -3.0e38f, tmax1 = -3.0e38f;
            #pragma unroll
            for (int nj = 0; nj < 8; nj++) {
                int2 ma = *(const int2*)(mbase + cb + nj * 8);
                int2 mb2 = *(const int2*)(mbase + 8 * (size_t)S + cb + nj * 8);
                sacc[nj][0] = ma.x  ? sacc[nj][0] : -1.0e9f;
                sacc[nj][1] = ma.y  ? sacc[nj][1] : -1.0e9f;
                sacc[nj][2] = mb2.x ? sacc[nj][2] : -1.0e9f;
                sacc[nj][3] = mb2.y ? sacc[nj][3] : -1.0e9f;
                tmax0 = fmaxf(tmax0, fmaxf(sacc[nj][0], sacc[nj][1]));
                tmax1 = fmaxf(tmax1, fmaxf(sacc[nj][2], sacc[nj][3]));
            }
            tmax0 = fmaxf(tmax0, __shfl_xor_sync(0xffffffffu, tmax0, 1));
            tmax0 = fmaxf(tmax0, __shfl_xor_sync(0xffffffffu, tmax0, 2));
            tmax1 = fmaxf(tmax1, __shfl_xor_sync(0xffffffffu, tmax1, 1));
            tmax1 = fmaxf(tmax1, __shfl_xor_sync(0xffffffffu, tmax1, 2));

            float mn0 = fmaxf(mrow0, tmax0), mn1 = fmaxf(mrow1, tmax1);
            float al0 = ex2f(mrow0 - mn0), al1 = ex2f(mrow1 - mn1);
            mrow0 = mn0; mrow1 = mn1;

            // --- exp + row sums ---
            float s0 = 0.f, s1 = 0.f;
            #pragma unroll
            for (int nj = 0; nj < 8; nj++) {
                sacc[nj][0] = ex2f(sacc[nj][0] - mn0);
                sacc[nj][1] = ex2f(sacc[nj][1] - mn0);
                sacc[nj][2] = ex2f(sacc[nj][2] - mn1);
                sacc[nj][3] = ex2f(sacc[nj][3] - mn1);
                s0 += sacc[nj][0] + sacc[nj][1];
                s1 += sacc[nj][2] + sacc[nj][3];
            }
            s0 += __shfl_xor_sync(0xffffffffu, s0, 1);
            s0 += __shfl_xor_sync(0xffffffffu, s0, 2);
            s1 += __shfl_xor_sync(0xffffffffu, s1, 1);
            s1 += __shfl_xor_sync(0xffffffffu, s1, 2);
            lrow0 = lrow0 * al0 + s0;
            lrow1 = lrow1 * al1 + s1;

            // --- rescale O ---
            #pragma unroll
            for (int nj = 0; nj < 8; nj++) {
                oacc[nj][0] *= al0; oacc[nj][1] *= al0;
                oacc[nj][2] *= al1; oacc[nj][3] *= al1;
            }

            // --- PV: P (regs) x V (smem, trans) ---
            #pragma unroll
            for (int ks = 0; ks < 4; ks++) {
                const float* cA = sacc[2 * ks];
                const float* cB = sacc[2 * ks + 1];
                float hA0 = bf16rnd(cA[0]), hA1 = bf16rnd(cA[1]);
                float hA2 = bf16rnd(cA[2]), hA3 = bf16rnd(cA[3]);
                float hB0 = bf16rnd(cB[0]), hB1 = bf16rnd(cB[1]);
                float hB2 = bf16rnd(cB[2]), hB3 = bf16rnd(cB[3]);
                uint32_t aph[4] = { pack_bf16x2(hA0, hA1), pack_bf16x2(hA2, hA3),
                                    pack_bf16x2(hB0, hB1), pack_bf16x2(hB2, hB3) };
                uint32_t apl[4] = { pack_bf16x2(cA[0] - hA0, cA[1] - hA1),
                                    pack_bf16x2(cA[2] - hA2, cA[3] - hA3),
                                    pack_bf16x2(cB[0] - hB0, cB[1] - hB1),
                                    pack_bf16x2(cB[2] - hB2, cB[3] - hB3) };
                #pragma unroll
                for (int p = 0; p < 4; p++) {
                    uint32_t rb = vb
                        + (uint32_t)(half * 64 + ks * 16 + (lmat & 1) * 8 + lr) * QSTR
                        + (p * 16 + (lmat >> 1) * 8) * 2;
                    uint32_t t[4], u[4];
                    ldsm4t(t, rb);
                    ldsm4t(u, rb + 18432);
                    mma_bf16(oacc[2 * p],     aph, t + 0);
                    mma_bf16(oacc[2 * p],     apl, t + 0);
                    mma_bf16(oacc[2 * p],     aph, u + 0);
                    mma_bf16(oacc[2 * p + 1], aph, t + 2);
                    mma_bf16(oacc[2 * p + 1], apl, t + 2);
                    mma_bf16(oacc[2 * p + 1], aph, u + 2);
                }
            }
        }
        __syncthreads();
    }

    // --- epilogue: O / l -> g_X ---
    float i0 = 1.f / lrow0, i1 = 1.f / lrow1;
    float* Og = g_X + ((size_t)b * S + q0) * DMODEL + h * DKH;
    const int rl0 = qrow + (lane >> 2);
    #pragma unroll
    for (int nj = 0; nj < 8; nj++) {
        int col = nj * 8 + (lane & 3) * 2;
        *(float2*)(Og + (size_t)rl0 * DMODEL + col) =
            make_float2(oacc[nj][0] * i0, oacc[nj][1] * i0);
        *(float2*)(Og + (size_t)(rl0 + 8) * DMODEL + col) =
            make_float2(oacc[nj][2] * i1, oacc[nj][3] * i1);
    }
}

// ---------------------------------------------------------------------------
extern "C" void kernel_launch(void* const* d_in, const int* in_sizes, int n_in,
                              void* d_out, int out_size)
{
    const float* q  = (const float*)d_in[0];
    const float* k  = (const float*)d_in[1];
    const float* v  = (const float*)d_in[2];
    const int* mask = (const int*)d_in[3];
    const float* w_q = (const float*)d_in[4];
    const float* w_k = (const float*)d_in[5];
    const float* w_v = (const float*)d_in[6];
    const float* w_o = (const float*)d_in[7];
    float* out = (float*)d_out;

    const int M = in_sizes[0] / DMODEL;                       // B*S = 4096
    const int S = (int)(((long long)in_sizes[3]) / M);        // 2048
    const int B = M / S;                                      // 2

    float* gx;
    __nv_bfloat16 *qh, *ql, *kh, *kl, *vh, *vl;
    cudaGetSymbolAddress((void**)&gx, g_X);
    cudaGetSymbolAddress((void**)&qh, g_Qh);
    cudaGetSymbolAddress((void**)&ql, g_Ql);
    cudaGetSymbolAddress((void**)&kh, g_Kh);
    cudaGetSymbolAddress((void**)&kl, g_Kl);
    cudaGetSymbolAddress((void**)&vh, g_Vh);
    cudaGetSymbolAddress((void**)&vl, g_Vl);

    cudaFuncSetAttribute(gemm_tc_nt,
                         cudaFuncAttributeMaxDynamicSharedMemorySize, GEMM_SMEM);
    cudaFuncSetAttribute(flash_attn_tc,
                         cudaFuncAttributeMaxDynamicSharedMemorySize, ATTN_SMEM);

    const float qscale = 0.125f * 1.44269504f;  // 1/sqrt(64) * log2(e)

    dim3 gg(DMODEL / 128, M / 128);
    gemm_tc_nt<<<gg, 256, GEMM_SMEM>>>(q, w_q, nullptr, qh, ql, M, DMODEL, DMODEL, qscale);
    gemm_tc_nt<<<gg, 256, GEMM_SMEM>>>(k, w_k, nullptr, kh, kl, M, DMODEL, DMODEL, 1.f);
    gemm_tc_nt<<<gg, 256, GEMM_SMEM>>>(v, w_v, nullptr, vh, vl, M, DMODEL, DMODEL, 1.f);

    dim3 ga(S / 128, NHEADS, B);
    flash_attn_tc<<<ga, 256, ATTN_SMEM>>>(mask, S);

    gemm_tc_nt<<<gg, 256, GEMM_SMEM>>>(gx, w_o, out, nullptr, nullptr, M, DMODEL, DMODEL, 1.f);
}

// round 8
// speedup vs baseline: 3.3015x; 1.1273x over previous
#include <cuda_runtime.h>
#include <cuda_bf16.h>
#include <cstdint>

#define DMODEL 1024
#define NHEADS 16
#define DKH    64

// Scratch (__device__ globals per allocation rules).
__device__ __nv_bfloat16 g_INh[3][4194304], g_INl[3][4194304];  // split q,k,v inputs
__device__ __nv_bfloat16 g_WWh[4][1048576], g_WWl[4][1048576];  // split weights
__device__ __nv_bfloat16 g_Qh[4194304], g_Ql[4194304];          // projected Q/K/V (split)
__device__ __nv_bfloat16 g_Kh[4194304], g_Kl[4194304];
__device__ __nv_bfloat16 g_Vh[4194304], g_Vl[4194304];
__device__ __nv_bfloat16 g_Xh[4194304], g_Xl[4194304];          // attention out (split)

// ===========================================================================
// helpers (generic PTX, compute_103-safe)
// ===========================================================================
__device__ __forceinline__ uint32_t smem_u32(const void* p) {
    uint32_t a;
    asm("{ .reg .u64 t; cvta.to.shared.u64 t, %1; cvt.u32.u64 %0, t; }"
        : "=r"(a) : "l"(p));
    return a;
}
__device__ __forceinline__ void ldsm4(uint32_t* r, uint32_t a) {
    asm volatile("ldmatrix.sync.aligned.m8n8.x4.shared.b16 {%0,%1,%2,%3}, [%4];"
                 : "=r"(r[0]), "=r"(r[1]), "=r"(r[2]), "=r"(r[3]) : "r"(a));
}
__device__ __forceinline__ void ldsm4t(uint32_t* r, uint32_t a) {
    asm volatile("ldmatrix.sync.aligned.m8n8.x4.trans.shared.b16 {%0,%1,%2,%3}, [%4];"
                 : "=r"(r[0]), "=r"(r[1]), "=r"(r[2]), "=r"(r[3]) : "r"(a));
}
__device__ __forceinline__ void mma_bf16(float* c, const uint32_t* a, const uint32_t* b) {
    asm volatile("mma.sync.aligned.m16n8k16.row.col.f32.bf16.bf16.f32 "
                 "{%0,%1,%2,%3}, {%4,%5,%6,%7}, {%8,%9}, {%0,%1,%2,%3};"
                 : "+f"(c[0]), "+f"(c[1]), "+f"(c[2]), "+f"(c[3])
                 : "r"(a[0]), "r"(a[1]), "r"(a[2]), "r"(a[3]),
                   "r"(b[0]), "r"(b[1]));
}
__device__ __forceinline__ uint32_t pack_bf16x2(float a, float b) {
    __nv_bfloat162 t = __floats2bfloat162_rn(a, b);
    return *reinterpret_cast<uint32_t*>(&t);
}
__device__ __forceinline__ void split4(float4 v, uint2& hi, uint2& lo) {
    float h0 = __bfloat162float(__float2bfloat16(v.x));
    float h1 = __bfloat162float(__float2bfloat16(v.y));
    float h2 = __bfloat162float(__float2bfloat16(v.z));
    float h3 = __bfloat162float(__float2bfloat16(v.w));
    hi = make_uint2(pack_bf16x2(h0, h1), pack_bf16x2(h2, h3));
    lo = make_uint2(pack_bf16x2(v.x - h0, v.y - h1), pack_bf16x2(v.z - h2, v.w - h3));
}
__device__ __forceinline__ float ex2f(float x) {
    float y;
    asm("ex2.approx.f32 %0, %1;" : "=f"(y) : "f"(x));
    return y;
}
__device__ __forceinline__ float bf16rnd(float x) {
    return __bfloat162float(__float2bfloat16(x));
}
__device__ __forceinline__ void cp16(uint32_t dst, const void* src) {
    asm volatile("cp.async.cg.shared.global [%0], [%1], 16;" :: "r"(dst), "l"(src));
}
#define CP_COMMIT() asm volatile("cp.async.commit_group;" ::: "memory")
#define CP_WAIT1()  asm volatile("cp.async.wait_group 1;" ::: "memory")
#define CP_WAIT0()  asm volatile("cp.async.wait_group 0;" ::: "memory")

// ===========================================================================
// split kernel: fp32 -> bf16 hi + residual lo
// ===========================================================================
__global__ __launch_bounds__(256) void split_f32(
    const float4* __restrict__ src, uint2* __restrict__ hi,
    uint2* __restrict__ lo, int n4)
{
    int i = blockIdx.x * 256 + threadIdx.x;
    if (i < n4) {
        uint2 h, l;
        split4(src[i], h, l);
        hi[i] = h;
        lo[i] = l;
    }
}

// ===========================================================================
// GEMM on pre-split operands: C = (Ah+Al)[M,K] @ (Bh+Bl)[N,K]^T * scale
// 3-term (AhBh + AhBl + AlBh). 128x128 tile, BK=64, 3-stage cp.async.
// Output: fp32 C or pre-split bf16 (Chi/Clo).
// ===========================================================================
#define GTILE 18432                // 128 rows * 144B (64 bf16 + 16B pad)
#define GSTG  (4 * GTILE)          // Ah, Al, Bh, Bl
#define NSTG  3
#define GEMM_SMEM (NSTG * GSTG)    // 221184

__global__ __launch_bounds__(256) void gemm_ps(
    const __nv_bfloat16* __restrict__ Ah, const __nv_bfloat16* __restrict__ Al,
    const __nv_bfloat16* __restrict__ Bh, const __nv_bfloat16* __restrict__ Bl,
    float* __restrict__ C, __nv_bfloat16* __restrict__ Chi,
    __nv_bfloat16* __restrict__ Clo,
    int M, int N, int K, float scale)
{
    extern __shared__ char smraw[];
    const uint32_t sb = smem_u32(smraw);
    const int tid = threadIdx.x, wid = tid >> 5, lane = tid & 31;
    const int wm = wid >> 1, wn = wid & 1;
    const int m0 = blockIdx.y * 128, n0 = blockIdx.x * 128;
    const int lr = lane & 7, lmat = lane >> 3;

    float acc[2][8][4];
    #pragma unroll
    for (int i = 0; i < 2; i++)
        #pragma unroll
        for (int j = 0; j < 8; j++)
            #pragma unroll
            for (int t = 0; t < 4; t++) acc[i][j][t] = 0.f;

    const int NC = K / 64;

    auto issue = [&](int stg, int kc) {
        uint32_t dstb = sb + stg * GSTG;
        #pragma unroll
        for (int s = 0; s < 16; s++) {
            int arr = s >> 2;
            int cc = ((s & 3) << 8) + tid;      // 0..1023
            int row = cc >> 3, off = cc & 7;
            uint32_t d = dstb + arr * GTILE + row * 144 + off * 16;
            const __nv_bfloat16* sp;
            if (arr == 0)      sp = Ah + (size_t)(m0 + row) * K + kc + off * 8;
            else if (arr == 1) sp = Al + (size_t)(m0 + row) * K + kc + off * 8;
            else if (arr == 2) sp = Bh + (size_t)(n0 + row) * K + kc + off * 8;
            else               sp = Bl + (size_t)(n0 + row) * K + kc + off * 8;
            cp16(d, sp);
        }
    };

    issue(0, 0);  CP_COMMIT();
    issue(1, 64); CP_COMMIT();

    for (int i = 0; i < NC; i++) {
        if (i < NC - 1) CP_WAIT1(); else CP_WAIT0();
        __syncthreads();

        const uint32_t stb = sb + (i % NSTG) * GSTG;
        #pragma unroll
        for (int ks = 0; ks < 4; ks++) {
            uint32_t ah[2][4], al[2][4];
            #pragma unroll
            for (int mi = 0; mi < 2; mi++) {
                uint32_t ra = stb
                    + (uint32_t)(wm * 32 + mi * 16 + lr + (lmat & 1) * 8) * 144
                    + (ks * 16 + (lmat >> 1) * 8) * 2;
                ldsm4(ah[mi], ra);
                ldsm4(al[mi], ra + GTILE);
            }
            #pragma unroll
            for (int p = 0; p < 4; p++) {
                uint32_t rb = stb + 2 * GTILE
                    + (uint32_t)(wn * 64 + p * 16 + (lmat >> 1) * 8 + lr) * 144
                    + (ks * 16 + (lmat & 1) * 8) * 2;
                uint32_t t[4], u[4];
                ldsm4(t, rb);
                ldsm4(u, rb + GTILE);
                #pragma unroll
                for (int mi = 0; mi < 2; mi++) {
                    mma_bf16(acc[mi][2 * p],     ah[mi], t + 0);
                    mma_bf16(acc[mi][2 * p],     ah[mi], u + 0);
                    mma_bf16(acc[mi][2 * p],     al[mi], t + 0);
                    mma_bf16(acc[mi][2 * p + 1], ah[mi], t + 2);
                    mma_bf16(acc[mi][2 * p + 1], ah[mi], u + 2);
                    mma_bf16(acc[mi][2 * p + 1], al[mi], t + 2);
                }
            }
        }

        if (i + 2 < NC) { issue((i + 2) % NSTG, (i + 2) * 64); CP_COMMIT(); }
    }

    // epilogue
    #pragma unroll
    for (int mi = 0; mi < 2; mi++) {
        int r0 = m0 + wm * 32 + mi * 16 + (lane >> 2);
        #pragma unroll
        for (int nj = 0; nj < 8; nj++) {
            int col = n0 + wn * 64 + nj * 8 + (lane & 3) * 2;
            float c0 = acc[mi][nj][0] * scale, c1 = acc[mi][nj][1] * scale;
            float c2 = acc[mi][nj][2] * scale, c3 = acc[mi][nj][3] * scale;
            if (Chi) {
                float h0 = bf16rnd(c0), h1 = bf16rnd(c1);
                float h2 = bf16rnd(c2), h3 = bf16rnd(c3);
                *(uint32_t*)(Chi + (size_t)r0 * N + col)       = pack_bf16x2(h0, h1);
                *(uint32_t*)(Clo + (size_t)r0 * N + col)       = pack_bf16x2(c0 - h0, c1 - h1);
                *(uint32_t*)(Chi + (size_t)(r0 + 8) * N + col) = pack_bf16x2(h2, h3);
                *(uint32_t*)(Clo + (size_t)(r0 + 8) * N + col) = pack_bf16x2(c2 - h2, c3 - h3);
            } else {
                *(float2*)(C + (size_t)r0 * N + col)       = make_float2(c0, c1);
                *(float2*)(C + (size_t)(r0 + 8) * N + col) = make_float2(c2, c3);
            }
        }
    }
}

// ===========================================================================
// Flash attention, FA2-style, 64-key tiles, 2 CTAs/SM target.
// Q pre-scaled by 0.125*log2e in projection; epilogue writes split output.
// ===========================================================================
#define QSTR 144
#define AQ_HI 0
#define AQ_LO 18432
#define ABUF0 36864
#define KVARR 9216                 // one 64x64 bf16 tile (144B rows)
#define KVBUF (4 * KVARR)          // Kh, Kl, Vh, Vl
#define ATTN_SMEM (ABUF0 + 2 * KVBUF)   // 110592

__global__ void __launch_bounds__(256, 2) flash_attn_tc(
    const int* __restrict__ mask, int S)
{
    extern __shared__ char smraw[];
    const uint32_t sb = smem_u32(smraw);
    const int tid = threadIdx.x, wid = tid >> 5, lane = tid & 31;
    const int lr = lane & 7, lmat = lane >> 3;
    const int b = blockIdx.z, h = blockIdx.y;
    const int q0 = blockIdx.x * 128;
    const int qrow = wid * 16;
    const size_t rowbase = (size_t)b * S;
    const size_t hoff = (size_t)h * DKH;

    // --- Q async load (hi/lo) ---
    {
        const __nv_bfloat16* Qhp = g_Qh + (rowbase + q0) * DMODEL + hoff;
        const __nv_bfloat16* Qlp = g_Ql + (rowbase + q0) * DMODEL + hoff;
        #pragma unroll
        for (int s = 0; s < 8; s++) {
            int arr = s >> 2;
            int cc = ((s & 3) << 8) + tid;
            int row = cc >> 3, off = cc & 7;
            cp16(sb + (arr ? AQ_LO : AQ_HI) + row * QSTR + off * 16,
                 (arr ? Qlp : Qhp) + (size_t)row * DMODEL + off * 8);
        }
    }

    auto issue_kv = [&](int buf, int k1) {
        size_t koff = (rowbase + k1) * DMODEL + hoff;
        const __nv_bfloat16* sp[4] = { g_Kh + koff, g_Kl + koff,
                                       g_Vh + koff, g_Vl + koff };
        uint32_t dstb = sb + ABUF0 + buf * KVBUF;
        #pragma unroll
        for (int s = 0; s < 8; s++) {
            int arr = s >> 1;
            int cc = ((s & 1) << 8) + tid;
            int row = cc >> 3, off = cc & 7;
            cp16(dstb + arr * KVARR + row * QSTR + off * 16,
                 sp[arr] + (size_t)row * DMODEL + off * 8);
        }
    };

    issue_kv(0, 0);
    CP_COMMIT();

    float oacc[8][4];
    #pragma unroll
    for (int j = 0; j < 8; j++)
        #pragma unroll
        for (int t = 0; t < 4; t++) oacc[j][t] = 0.f;
    float mrow0 = -3.0e38f, mrow1 = -3.0e38f, lrow0 = 0.f, lrow1 = 0.f;

    const int* mbase = mask + (rowbase + q0 + qrow + (lane >> 2)) * S;

    const int NT = S / 64;
    for (int it = 0; it < NT; it++) {
        if (it + 1 < NT) {
            issue_kv((it + 1) & 1, (it + 1) * 64);
            CP_COMMIT();
            CP_WAIT1();
        } else {
            CP_WAIT0();
        }
        __syncthreads();

        const uint32_t kb = sb + ABUF0 + (it & 1) * KVBUF;
        const uint32_t vb = kb + 2 * KVARR;

        float sacc[8][4];
        #pragma unroll
        for (int j = 0; j < 8; j++)
            #pragma unroll
            for (int t = 0; t < 4; t++) sacc[j][t] = 0.f;

        // --- QK^T: 16q x 64k, d=64 ---
        #pragma unroll
        for (int ks = 0; ks < 4; ks++) {
            uint32_t qh[4], ql[4];
            uint32_t ra = sb + AQ_HI
                + (uint32_t)(qrow + lr + (lmat & 1) * 8) * QSTR
                + (ks * 16 + (lmat >> 1) * 8) * 2;
            ldsm4(qh, ra);
            ldsm4(ql, ra + (AQ_LO - AQ_HI));
            #pragma unroll
            for (int p = 0; p < 4; p++) {
                uint32_t rb = kb
                    + (uint32_t)(p * 16 + (lmat >> 1) * 8 + lr) * QSTR
                    + (ks * 16 + (lmat & 1) * 8) * 2;
                uint32_t t[4], u[4];
                ldsm4(t, rb);
                ldsm4(u, rb + KVARR);
                mma_bf16(sacc[2 * p],     qh, t + 0);
                mma_bf16(sacc[2 * p],     qh, u + 0);
                mma_bf16(sacc[2 * p],     ql, t + 0);
                mma_bf16(sacc[2 * p + 1], qh, t + 2);
                mma_bf16(sacc[2 * p + 1], qh, u + 2);
                mma_bf16(sacc[2 * p + 1], ql, t + 2);
            }
        }

        // --- mask + row max (log2 domain) ---
        const int* mp = mbase + it * 64 + (lane & 3) * 2;
        float tmax0 = -3.0e38f, tmax1 = -3.0e38f;
        #pragma unroll
        for (int nj = 0; nj < 8; nj++) {
            int2 ma  = *(const int2*)(mp + nj * 8);
            int2 mb2 = *(const int2*)(mp + 8 * (size_t)S + nj * 8);
            sacc[nj][0] = ma.x  ? sacc[nj][0] : -1.0e9f;
            sacc[nj][1] = ma.y  ? sacc[nj][1] : -1.0e9f;
            sacc[nj][2] = mb2.x ? sacc[nj][2] : -1.0e9f;
            sacc[nj][3] = mb2.y ? sacc[nj][3] : -1.0e9f;
            tmax0 = fmaxf(tmax0, fmaxf(sacc[nj][0], sacc[nj][1]));
            tmax1 = fmaxf(tmax1, fmaxf(sacc[nj][2], sacc[nj][3]));
        }
        tmax0 = fmaxf(tmax0, __shfl_xor_sync(0xffffffffu, tmax0, 1));
        tmax0 = fmaxf(tmax0, __shfl_xor_sync(0xffffffffu, tmax0, 2));
        tmax1 = fmaxf(tmax1, __shfl_xor_sync(0xffffffffu, tmax1, 1));
        tmax1 = fmaxf(tmax1, __shfl_xor_sync(0xffffffffu, tmax1, 2));

        float mn0 = fmaxf(mrow0, tmax0), mn1 = fmaxf(mrow1, tmax1);
        float al0 = ex2f(mrow0 - mn0), al1 = ex2f(mrow1 - mn1);
        mrow0 = mn0; mrow1 = mn1;

        // --- exp + row sums ---
        float s0 = 0.f, s1 = 0.f;
        #pragma unroll
        for (int nj = 0; nj < 8; nj++) {
            sacc[nj][0] = ex2f(sacc[nj][0] - mn0);
            sacc[nj][1] = ex2f(sacc[nj][1] - mn0);
            sacc[nj][2] = ex2f(sacc[nj][2] - mn1);
            sacc[nj][3] = ex2f(sacc[nj][3] - mn1);
            s0 += sacc[nj][0] + sacc[nj][1];
            s1 += sacc[nj][2] + sacc[nj][3];
        }
        s0 += __shfl_xor_sync(0xffffffffu, s0, 1);
        s0 += __shfl_xor_sync(0xffffffffu, s0, 2);
        s1 += __shfl_xor_sync(0xffffffffu, s1, 1);
        s1 += __shfl_xor_sync(0xffffffffu, s1, 2);
        lrow0 = lrow0 * al0 + s0;
        lrow1 = lrow1 * al1 + s1;

        // --- rescale O ---
        #pragma unroll
        for (int nj = 0; nj < 8; nj++) {
            oacc[nj][0] *= al0; oacc[nj][1] *= al0;
            oacc[nj][2] *= al1; oacc[nj][3] *= al1;
        }

        // --- PV: P (regs, split) x V (smem, trans) ---
        #pragma unroll
        for (int ks = 0; ks < 4; ks++) {
            const float* cA = sacc[2 * ks];
            const float* cB = sacc[2 * ks + 1];
            float hA0 = bf16rnd(cA[0]), hA1 = bf16rnd(cA[1]);
            float hA2 = bf16rnd(cA[2]), hA3 = bf16rnd(cA[3]);
            float hB0 = bf16rnd(cB[0]), hB1 = bf16rnd(cB[1]);
            float hB2 = bf16rnd(cB[2]), hB3 = bf16rnd(cB[3]);
            uint32_t aph[4] = { pack_bf16x2(hA0, hA1), pack_bf16x2(hA2, hA3),
                                pack_bf16x2(hB0, hB1), pack_bf16x2(hB2, hB3) };
            uint32_t apl[4] = { pack_bf16x2(cA[0] - hA0, cA[1] - hA1),
                                pack_bf16x2(cA[2] - hA2, cA[3] - hA3),
                                pack_bf16x2(cB[0] - hB0, cB[1] - hB1),
                                pack_bf16x2(cB[2] - hB2, cB[3] - hB3) };
            #pragma unroll
            for (int p = 0; p < 4; p++) {
                uint32_t rb = vb
                    + (uint32_t)(ks * 16 + (lmat & 1) * 8 + lr) * QSTR
                    + (p * 16 + (lmat >> 1) * 8) * 2;
                uint32_t t[4], u[4];
                ldsm4t(t, rb);
                ldsm4t(u, rb + KVARR);
                mma_bf16(oacc[2 * p],     aph, t + 0);
                mma_bf16(oacc[2 * p],     apl, t + 0);
                mma_bf16(oacc[2 * p],     aph, u + 0);
                mma_bf16(oacc[2 * p + 1], aph, t + 2);
                mma_bf16(oacc[2 * p + 1], apl, t + 2);
                mma_bf16(oacc[2 * p + 1], aph, u + 2);
            }
        }
        __syncthreads();
    }

    // --- epilogue: O / l, written pre-split for the w_o GEMM ---
    float i0 = 1.f / lrow0, i1 = 1.f / lrow1;
    __nv_bfloat16* Xh = g_Xh + (rowbase + q0) * DMODEL + hoff;
    __nv_bfloat16* Xl = g_Xl + (rowbase + q0) * DMODEL + hoff;
    const int rl0 = qrow + (lane >> 2);
    #pragma unroll
    for (int nj = 0; nj < 8; nj++) {
        int col = nj * 8 + (lane & 3) * 2;
        float c0 = oacc[nj][0] * i0, c1 = oacc[nj][1] * i0;
        float c2 = oacc[nj][2] * i1, c3 = oacc[nj][3] * i1;
        float h0 = bf16rnd(c0), h1 = bf16rnd(c1);
        float h2 = bf16rnd(c2), h3 = bf16rnd(c3);
        *(uint32_t*)(Xh + (size_t)rl0 * DMODEL + col)       = pack_bf16x2(h0, h1);
        *(uint32_t*)(Xl + (size_t)rl0 * DMODEL + col)       = pack_bf16x2(c0 - h0, c1 - h1);
        *(uint32_t*)(Xh + (size_t)(rl0 + 8) * DMODEL + col) = pack_bf16x2(h2, h3);
        *(uint32_t*)(Xl + (size_t)(rl0 + 8) * DMODEL + col) = pack_bf16x2(c2 - h2, c3 - h3);
    }
}

// ---------------------------------------------------------------------------
extern "C" void kernel_launch(void* const* d_in, const int* in_sizes, int n_in,
                              void* d_out, int out_size)
{
    const float* q  = (const float*)d_in[0];
    const float* k  = (const float*)d_in[1];
    const float* v  = (const float*)d_in[2];
    const int* mask = (const int*)d_in[3];
    const float* w[4] = { (const float*)d_in[4], (const float*)d_in[5],
                          (const float*)d_in[6], (const float*)d_in[7] };
    float* out = (float*)d_out;

    const int M = in_sizes[0] / DMODEL;                       // B*S = 4096
    const int S = (int)(((long long)in_sizes[3]) / M);        // 2048
    const int B = M / S;                                      // 2

    __nv_bfloat16 *inh, *inl, *wwh, *wwl;
    __nv_bfloat16 *qh, *ql, *kh, *kl, *vh, *vl, *xh, *xl;
    cudaGetSymbolAddress((void**)&inh, g_INh);
    cudaGetSymbolAddress((void**)&inl, g_INl);
    cudaGetSymbolAddress((void**)&wwh, g_WWh);
    cudaGetSymbolAddress((void**)&wwl, g_WWl);
    cudaGetSymbolAddress((void**)&qh, g_Qh);
    cudaGetSymbolAddress((void**)&ql, g_Ql);
    cudaGetSymbolAddress((void**)&kh, g_Kh);
    cudaGetSymbolAddress((void**)&kl, g_Kl);
    cudaGetSymbolAddress((void**)&vh, g_Vh);
    cudaGetSymbolAddress((void**)&vl, g_Vl);
    cudaGetSymbolAddress((void**)&xh, g_Xh);
    cudaGetSymbolAddress((void**)&xl, g_Xl);

    cudaFuncSetAttribute(gemm_ps,
                         cudaFuncAttributeMaxDynamicSharedMemorySize, GEMM_SMEM);
    cudaFuncSetAttribute(flash_attn_tc,
                         cudaFuncAttributeMaxDynamicSharedMemorySize, ATTN_SMEM);

    const int AE = M * DMODEL;          // 4M activation elements
    const int WE = DMODEL * DMODEL;     // 1M weight elements
    const float* act[3] = { q, k, v };

    // --- split inputs ---
    for (int i = 0; i < 3; i++)
        split_f32<<<AE / 1024, 256>>>((const float4*)act[i],
                                      (uint2*)(inh + (size_t)i * AE),
                                      (uint2*)(inl + (size_t)i * AE), AE / 4);
    for (int i = 0; i < 4; i++)
        split_f32<<<WE / 1024, 256>>>((const float4*)w[i],
                                      (uint2*)(wwh + (size_t)i * WE),
                                      (uint2*)(wwl + (size_t)i * WE), WE / 4);

    const float qscale = 0.125f * 1.44269504f;  // 1/sqrt(64) * log2(e)

    dim3 gg(DMODEL / 128, M / 128);
    gemm_ps<<<gg, 256, GEMM_SMEM>>>(inh,          inl,          wwh,          wwl,
                                    nullptr, qh, ql, M, DMODEL, DMODEL, qscale);
    gemm_ps<<<gg, 256, GEMM_SMEM>>>(inh + AE,     inl + AE,     wwh + WE,     wwl + WE,
                                    nullptr, kh, kl, M, DMODEL, DMODEL, 1.f);
    gemm_ps<<<gg, 256, GEMM_SMEM>>>(inh + 2 * AE, inl + 2 * AE, wwh + 2 * WE, wwl + 2 * WE,
                                    nullptr, vh, vl, M, DMODEL, DMODEL, 1.f);

    dim3 ga(S / 128, NHEADS, B);
    flash_attn_tc<<<ga, 256, ATTN_SMEM>>>(mask, S);

    gemm_ps<<<gg, 256, GEMM_SMEM>>>(xh, xl, wwh + 3 * WE, wwl + 3 * WE,
                                    out, nullptr, nullptr, M, DMODEL, DMODEL, 1.f);
}

// round 9
// speedup vs baseline: 3.5235x; 1.0672x over previous
#include <cuda_runtime.h>
#include <cuda_bf16.h>
#include <cstdint>

#define DMODEL 1024
#define NHEADS 16
#define DKH    64

// Scratch (__device__ globals per allocation rules).
__device__ __nv_bfloat16 g_INh[3][4194304], g_INl[3][4194304];  // split q,k,v inputs
__device__ __nv_bfloat16 g_WWh[4][1048576], g_WWl[4][1048576];  // split weights
__device__ __nv_bfloat16 g_Qh[4194304], g_Ql[4194304];          // projected Q/K/V (split)
__device__ __nv_bfloat16 g_Kh[4194304], g_Kl[4194304];
__device__ __nv_bfloat16 g_Vh[4194304], g_Vl[4194304];
__device__ __nv_bfloat16 g_Xh[4194304], g_Xl[4194304];          // attention out (split)
__device__ uint32_t g_Mb[262144];                               // mask bitwords B*S*S/32

// ===========================================================================
// helpers (generic PTX, compute_103-safe)
// ===========================================================================
__device__ __forceinline__ uint32_t smem_u32(const void* p) {
    uint32_t a;
    asm("{ .reg .u64 t; cvta.to.shared.u64 t, %1; cvt.u32.u64 %0, t; }"
        : "=r"(a) : "l"(p));
    return a;
}
__device__ __forceinline__ void ldsm4(uint32_t* r, uint32_t a) {
    asm volatile("ldmatrix.sync.aligned.m8n8.x4.shared.b16 {%0,%1,%2,%3}, [%4];"
                 : "=r"(r[0]), "=r"(r[1]), "=r"(r[2]), "=r"(r[3]) : "r"(a));
}
__device__ __forceinline__ void ldsm4t(uint32_t* r, uint32_t a) {
    asm volatile("ldmatrix.sync.aligned.m8n8.x4.trans.shared.b16 {%0,%1,%2,%3}, [%4];"
                 : "=r"(r[0]), "=r"(r[1]), "=r"(r[2]), "=r"(r[3]) : "r"(a));
}
__device__ __forceinline__ void mma_bf16(float* c, const uint32_t* a, const uint32_t* b) {
    asm volatile("mma.sync.aligned.m16n8k16.row.col.f32.bf16.bf16.f32 "
                 "{%0,%1,%2,%3}, {%4,%5,%6,%7}, {%8,%9}, {%0,%1,%2,%3};"
                 : "+f"(c[0]), "+f"(c[1]), "+f"(c[2]), "+f"(c[3])
                 : "r"(a[0]), "r"(a[1]), "r"(a[2]), "r"(a[3]),
                   "r"(b[0]), "r"(b[1]));
}
__device__ __forceinline__ uint32_t pack_bf16x2(float a, float b) {
    __nv_bfloat162 t = __floats2bfloat162_rn(a, b);
    return *reinterpret_cast<uint32_t*>(&t);
}
__device__ __forceinline__ void split4(float4 v, uint2& hi, uint2& lo) {
    float h0 = __bfloat162float(__float2bfloat16(v.x));
    float h1 = __bfloat162float(__float2bfloat16(v.y));
    float h2 = __bfloat162float(__float2bfloat16(v.z));
    float h3 = __bfloat162float(__float2bfloat16(v.w));
    hi = make_uint2(pack_bf16x2(h0, h1), pack_bf16x2(h2, h3));
    lo = make_uint2(pack_bf16x2(v.x - h0, v.y - h1), pack_bf16x2(v.z - h2, v.w - h3));
}
__device__ __forceinline__ float ex2f(float x) {
    float y;
    asm("ex2.approx.f32 %0, %1;" : "=f"(y) : "f"(x));
    return y;
}
__device__ __forceinline__ float bf16rnd(float x) {
    return __bfloat162float(__float2bfloat16(x));
}
__device__ __forceinline__ void cp16(uint32_t dst, const void* src) {
    asm volatile("cp.async.cg.shared.global [%0], [%1], 16;" :: "r"(dst), "l"(src));
}
#define CP_COMMIT() asm volatile("cp.async.commit_group;" ::: "memory")
#define CP_WAIT1()  asm volatile("cp.async.wait_group 1;" ::: "memory")
#define CP_WAIT0()  asm volatile("cp.async.wait_group 0;" ::: "memory")

// ===========================================================================
// split kernel: fp32 -> bf16 hi + residual lo
// ===========================================================================
__global__ __launch_bounds__(256) void split_f32(
    const float4* __restrict__ src, uint2* __restrict__ hi,
    uint2* __restrict__ lo, int n4)
{
    int i = blockIdx.x * 256 + threadIdx.x;
    if (i < n4) {
        uint2 h, l;
        split4(src[i], h, l);
        hi[i] = h;
        lo[i] = l;
    }
}

// ===========================================================================
// mask -> bitwords (1 bit per mask element), warp ballot
// ===========================================================================
__global__ __launch_bounds__(256) void mask_bits(
    const int* __restrict__ m, uint32_t* __restrict__ bits)
{
    int w = blockIdx.x * 8 + (threadIdx.x >> 5);
    int lane = threadIdx.x & 31;
    const int* base = m + (size_t)w * 1024;
    uint32_t* ob = bits + (size_t)w * 32;
    #pragma unroll
    for (int t = 0; t < 32; t++) {
        int v = base[t * 32 + lane];
        uint32_t bb = __ballot_sync(0xffffffffu, v != 0);
        if (lane == 0) ob[t] = bb;
    }
}

// ===========================================================================
// GEMM core on pre-split operands: C = (Ah+Al)[M,K] @ (Bh+Bl)[N,K]^T * scale
// 3-term. 128x128 tile, BK=64, 3-stage cp.async.
// ===========================================================================
#define GTILE 18432                // 128 rows * 144B (64 bf16 + 16B pad)
#define GSTG  (4 * GTILE)          // Ah, Al, Bh, Bl
#define NSTG  3
#define GEMM_SMEM (NSTG * GSTG)    // 221184

__device__ __forceinline__ void gemm_core(
    const __nv_bfloat16* __restrict__ Ah, const __nv_bfloat16* __restrict__ Al,
    const __nv_bfloat16* __restrict__ Bh, const __nv_bfloat16* __restrict__ Bl,
    float* __restrict__ C, __nv_bfloat16* __restrict__ Chi,
    __nv_bfloat16* __restrict__ Clo,
    int M, int N, int K, float scale, char* smraw)
{
    const uint32_t sb = smem_u32(smraw);
    const int tid = threadIdx.x, wid = tid >> 5, lane = tid & 31;
    const int wm = wid >> 1, wn = wid & 1;
    const int m0 = blockIdx.y * 128, n0 = blockIdx.x * 128;
    const int lr = lane & 7, lmat = lane >> 3;

    float acc[2][8][4];
    #pragma unroll
    for (int i = 0; i < 2; i++)
        #pragma unroll
        for (int j = 0; j < 8; j++)
            #pragma unroll
            for (int t = 0; t < 4; t++) acc[i][j][t] = 0.f;

    const int NC = K / 64;

    auto issue = [&](int stg, int kc) {
        uint32_t dstb = sb + stg * GSTG;
        #pragma unroll
        for (int s = 0; s < 16; s++) {
            int arr = s >> 2;
            int cc = ((s & 3) << 8) + tid;
            int row = cc >> 3, off = cc & 7;
            uint32_t d = dstb + arr * GTILE + row * 144 + off * 16;
            const __nv_bfloat16* sp;
            if (arr == 0)      sp = Ah + (size_t)(m0 + row) * K + kc + off * 8;
            else if (arr == 1) sp = Al + (size_t)(m0 + row) * K + kc + off * 8;
            else if (arr == 2) sp = Bh + (size_t)(n0 + row) * K + kc + off * 8;
            else               sp = Bl + (size_t)(n0 + row) * K + kc + off * 8;
            cp16(d, sp);
        }
    };

    issue(0, 0);  CP_COMMIT();
    issue(1, 64); CP_COMMIT();

    for (int i = 0; i < NC; i++) {
        if (i < NC - 1) CP_WAIT1(); else CP_WAIT0();
        __syncthreads();

        const uint32_t stb = sb + (i % NSTG) * GSTG;
        #pragma unroll
        for (int ks = 0; ks < 4; ks++) {
            uint32_t ah[2][4], al[2][4];
            #pragma unroll
            for (int mi = 0; mi < 2; mi++) {
                uint32_t ra = stb
                    + (uint32_t)(wm * 32 + mi * 16 + lr + (lmat & 1) * 8) * 144
                    + (ks * 16 + (lmat >> 1) * 8) * 2;
                ldsm4(ah[mi], ra);
                ldsm4(al[mi], ra + GTILE);
            }
            #pragma unroll
            for (int p = 0; p < 4; p++) {
                uint32_t rb = stb + 2 * GTILE
                    + (uint32_t)(wn * 64 + p * 16 + (lmat >> 1) * 8 + lr) * 144
                    + (ks * 16 + (lmat & 1) * 8) * 2;
                uint32_t t[4], u[4];
                ldsm4(t, rb);
                ldsm4(u, rb + GTILE);
                #pragma unroll
                for (int mi = 0; mi < 2; mi++) {
                    mma_bf16(acc[mi][2 * p],     ah[mi], t + 0);
                    mma_bf16(acc[mi][2 * p],     ah[mi], u + 0);
                    mma_bf16(acc[mi][2 * p],     al[mi], t + 0);
                    mma_bf16(acc[mi][2 * p + 1], ah[mi], t + 2);
                    mma_bf16(acc[mi][2 * p + 1], ah[mi], u + 2);
                    mma_bf16(acc[mi][2 * p + 1], al[mi], t + 2);
                }
            }
        }

        if (i + 2 < NC) { issue((i + 2) % NSTG, (i + 2) * 64); CP_COMMIT(); }
    }

    #pragma unroll
    for (int mi = 0; mi < 2; mi++) {
        int r0 = m0 + wm * 32 + mi * 16 + (lane >> 2);
        #pragma unroll
        for (int nj = 0; nj < 8; nj++) {
            int col = n0 + wn * 64 + nj * 8 + (lane & 3) * 2;
            float c0 = acc[mi][nj][0] * scale, c1 = acc[mi][nj][1] * scale;
            float c2 = acc[mi][nj][2] * scale, c3 = acc[mi][nj][3] * scale;
            if (Chi) {
                float h0 = bf16rnd(c0), h1 = bf16rnd(c1);
                float h2 = bf16rnd(c2), h3 = bf16rnd(c3);
                *(uint32_t*)(Chi + (size_t)r0 * N + col)       = pack_bf16x2(h0, h1);
                *(uint32_t*)(Clo + (size_t)r0 * N + col)       = pack_bf16x2(c0 - h0, c1 - h1);
                *(uint32_t*)(Chi + (size_t)(r0 + 8) * N + col) = pack_bf16x2(h2, h3);
                *(uint32_t*)(Clo + (size_t)(r0 + 8) * N + col) = pack_bf16x2(c2 - h2, c3 - h3);
            } else {
                *(float2*)(C + (size_t)r0 * N + col)       = make_float2(c0, c1);
                *(float2*)(C + (size_t)(r0 + 8) * N + col) = make_float2(c2, c3);
            }
        }
    }
}

// Batched QKV projections: blockIdx.z picks operand set.
struct G3 {
    const __nv_bfloat16 *Ah, *Al, *Bh, *Bl;
    __nv_bfloat16 *Chi, *Clo;
    float scale;
};
struct Batch3 { G3 g[3]; };

__global__ __launch_bounds__(256) void gemm_qkv(Batch3 b, int M, int N, int K)
{
    extern __shared__ char smraw[];
    const G3& g = b.g[blockIdx.z];
    gemm_core(g.Ah, g.Al, g.Bh, g.Bl, nullptr, g.Chi, g.Clo, M, N, K, g.scale, smraw);
}

__global__ __launch_bounds__(256) void gemm_out(
    const __nv_bfloat16* __restrict__ Ah, const __nv_bfloat16* __restrict__ Al,
    const __nv_bfloat16* __restrict__ Bh, const __nv_bfloat16* __restrict__ Bl,
    float* __restrict__ C, int M, int N, int K)
{
    extern __shared__ char smraw[];
    gemm_core(Ah, Al, Bh, Bl, C, nullptr, nullptr, M, N, K, 1.f, smraw);
}

// ===========================================================================
// Flash attention, FA2-style, 64-key tiles, 2 CTAs/SM; bitmask mask path.
// Q pre-scaled by 0.125*log2e in projection; epilogue writes split output.
// ===========================================================================
#define QSTR 144
#define AQ_HI 0
#define AQ_LO 18432
#define ABUF0 36864
#define KVARR 9216                 // one 64x64 bf16 tile (144B rows)
#define KVBUF (4 * KVARR)
#define ATTN_SMEM (ABUF0 + 2 * KVBUF)   // 110592

__global__ void __launch_bounds__(256, 2) flash_attn_tc(int S)
{
    extern __shared__ char smraw[];
    const uint32_t sb = smem_u32(smraw);
    const int tid = threadIdx.x, wid = tid >> 5, lane = tid & 31;
    const int lr = lane & 7, lmat = lane >> 3;
    const int b = blockIdx.z, h = blockIdx.y;
    const int q0 = blockIdx.x * 128;
    const int qrow = wid * 16;
    const size_t rowbase = (size_t)b * S;
    const size_t hoff = (size_t)h * DKH;

    // --- Q async load (hi/lo) ---
    {
        const __nv_bfloat16* Qhp = g_Qh + (rowbase + q0) * DMODEL + hoff;
        const __nv_bfloat16* Qlp = g_Ql + (rowbase + q0) * DMODEL + hoff;
        #pragma unroll
        for (int s = 0; s < 8; s++) {
            int arr = s >> 2;
            int cc = ((s & 3) << 8) + tid;
            int row = cc >> 3, off = cc & 7;
            cp16(sb + (arr ? AQ_LO : AQ_HI) + row * QSTR + off * 16,
                 (arr ? Qlp : Qhp) + (size_t)row * DMODEL + off * 8);
        }
    }

    auto issue_kv = [&](int buf, int k1) {
        size_t koff = (rowbase + k1) * DMODEL + hoff;
        const __nv_bfloat16* sp[4] = { g_Kh + koff, g_Kl + koff,
                                       g_Vh + koff, g_Vl + koff };
        uint32_t dstb = sb + ABUF0 + buf * KVBUF;
        #pragma unroll
        for (int s = 0; s < 8; s++) {
            int arr = s >> 1;
            int cc = ((s & 1) << 8) + tid;
            int row = cc >> 3, off = cc & 7;
            cp16(dstb + arr * KVARR + row * QSTR + off * 16,
                 sp[arr] + (size_t)row * DMODEL + off * 8);
        }
    };

    issue_kv(0, 0);
    CP_COMMIT();

    float oacc[8][4];
    #pragma unroll
    for (int j = 0; j < 8; j++)
        #pragma unroll
        for (int t = 0; t < 4; t++) oacc[j][t] = 0.f;
    float mrow0 = -3.0e38f, mrow1 = -3.0e38f, lrow0 = 0.f, lrow1 = 0.f;

    const int WPR = S >> 5;   // bit-words per row
    const uint32_t* mwb = g_Mb + (rowbase + q0 + qrow + (lane >> 2)) * WPR;

    const int NT = S / 64;
    for (int it = 0; it < NT; it++) {
        // prefetch mask bitwords for this tile (2 rows x 64 bits)
        uint2 mw0 = *(const uint2*)(mwb + it * 2);
        uint2 mw8 = *(const uint2*)(mwb + (size_t)8 * WPR + it * 2);
        uint64_t w0 = ((uint64_t)mw0.y << 32) | mw0.x;
        uint64_t w8 = ((uint64_t)mw8.y << 32) | mw8.x;

        if (it + 1 < NT) {
            issue_kv((it + 1) & 1, (it + 1) * 64);
            CP_COMMIT();
            CP_WAIT1();
        } else {
            CP_WAIT0();
        }
        __syncthreads();

        const uint32_t kb = sb + ABUF0 + (it & 1) * KVBUF;
        const uint32_t vb = kb + 2 * KVARR;

        float sacc[8][4];
        #pragma unroll
        for (int j = 0; j < 8; j++)
            #pragma unroll
            for (int t = 0; t < 4; t++) sacc[j][t] = 0.f;

        // --- QK^T: 16q x 64k, d=64 ---
        #pragma unroll
        for (int ks = 0; ks < 4; ks++) {
            uint32_t qh[4], ql[4];
            uint32_t ra = sb + AQ_HI
                + (uint32_t)(qrow + lr + (lmat & 1) * 8) * QSTR
                + (ks * 16 + (lmat >> 1) * 8) * 2;
            ldsm4(qh, ra);
            ldsm4(ql, ra + (AQ_LO - AQ_HI));
            #pragma unroll
            for (int p = 0; p < 4; p++) {
                uint32_t rb = kb
                    + (uint32_t)(p * 16 + (lmat >> 1) * 8 + lr) * QSTR
                    + (ks * 16 + (lmat & 1) * 8) * 2;
                uint32_t t[4], u[4];
                ldsm4(t, rb);
                ldsm4(u, rb + KVARR);
                mma_bf16(sacc[2 * p],     qh, t + 0);
                mma_bf16(sacc[2 * p],     qh, u + 0);
                mma_bf16(sacc[2 * p],     ql, t + 0);
                mma_bf16(sacc[2 * p + 1], qh, t + 2);
                mma_bf16(sacc[2 * p + 1], qh, u + 2);
                mma_bf16(sacc[2 * p + 1], ql, t + 2);
            }
        }

        // --- mask via bitwords (fast path: fully unmasked tile) ---
        if ((w0 & w8) != ~0ull) {
            #pragma unroll
            for (int nj = 0; nj < 8; nj++) {
                int c0 = (lane & 3) * 2 + nj * 8;
                sacc[nj][0] = ((w0 >> c0) & 1)       ? sacc[nj][0] : -1.0e9f;
                sacc[nj][1] = ((w0 >> (c0 + 1)) & 1) ? sacc[nj][1] : -1.0e9f;
                sacc[nj][2] = ((w8 >> c0) & 1)       ? sacc[nj][2] : -1.0e9f;
                sacc[nj][3] = ((w8 >> (c0 + 1)) & 1) ? sacc[nj][3] : -1.0e9f;
            }
        }

        // --- row max (log2 domain) ---
        float tmax0 = -3.0e38f, tmax1 = -3.0e38f;
        #pragma unroll
        for (int nj = 0; nj < 8; nj++) {
            tmax0 = fmaxf(tmax0, fmaxf(sacc[nj][0], sacc[nj][1]));
            tmax1 = fmaxf(tmax1, fmaxf(sacc[nj][2], sacc[nj][3]));
        }
        tmax0 = fmaxf(tmax0, __shfl_xor_sync(0xffffffffu, tmax0, 1));
        tmax0 = fmaxf(tmax0, __shfl_xor_sync(0xffffffffu, tmax0, 2));
        tmax1 = fmaxf(tmax1, __shfl_xor_sync(0xffffffffu, tmax1, 1));
        tmax1 = fmaxf(tmax1, __shfl_xor_sync(0xffffffffu, tmax1, 2));

        float mn0 = fmaxf(mrow0, tmax0), mn1 = fmaxf(mrow1, tmax1);
        float al0 = ex2f(mrow0 - mn0), al1 = ex2f(mrow1 - mn1);
        mrow0 = mn0; mrow1 = mn1;

        // --- exp + row sums ---
        float s0 = 0.f, s1 = 0.f;
        #pragma unroll
        for (int nj = 0; nj < 8; nj++) {
            sacc[nj][0] = ex2f(sacc[nj][0] - mn0);
            sacc[nj][1] = ex2f(sacc[nj][1] - mn0);
            sacc[nj][2] = ex2f(sacc[nj][2] - mn1);
            sacc[nj][3] = ex2f(sacc[nj][3] - mn1);
            s0 += sacc[nj][0] + sacc[nj][1];
            s1 += sacc[nj][2] + sacc[nj][3];
        }
        s0 += __shfl_xor_sync(0xffffffffu, s0, 1);
        s0 += __shfl_xor_sync(0xffffffffu, s0, 2);
        s1 += __shfl_xor_sync(0xffffffffu, s1, 1);
        s1 += __shfl_xor_sync(0xffffffffu, s1, 2);
        lrow0 = lrow0 * al0 + s0;
        lrow1 = lrow1 * al1 + s1;

        // --- rescale O ---
        #pragma unroll
        for (int nj = 0; nj < 8; nj++) {
            oacc[nj][0] *= al0; oacc[nj][1] *= al0;
            oacc[nj][2] *= al1; oacc[nj][3] *= al1;
        }

        // --- PV: P (regs, split) x V (smem, trans) ---
        #pragma unroll
        for (int ks = 0; ks < 4; ks++) {
            const float* cA = sacc[2 * ks];
            const float* cB = sacc[2 * ks + 1];
            float hA0 = bf16rnd(cA[0]), hA1 = bf16rnd(cA[1]);
            float hA2 = bf16rnd(cA[2]), hA3 = bf16rnd(cA[3]);
            float hB0 = bf16rnd(cB[0]), hB1 = bf16rnd(cB[1]);
            float hB2 = bf16rnd(cB[2]), hB3 = bf16rnd(cB[3]);
            uint32_t aph[4] = { pack_bf16x2(hA0, hA1), pack_bf16x2(hA2, hA3),
                                pack_bf16x2(hB0, hB1), pack_bf16x2(hB2, hB3) };
            uint32_t apl[4] = { pack_bf16x2(cA[0] - hA0, cA[1] - hA1),
                                pack_bf16x2(cA[2] - hA2, cA[3] - hA3),
                                pack_bf16x2(cB[0] - hB0, cB[1] - hB1),
                                pack_bf16x2(cB[2] - hB2, cB[3] - hB3) };
            #pragma unroll
            for (int p = 0; p < 4; p++) {
                uint32_t rb = vb
                    + (uint32_t)(ks * 16 + (lmat & 1) * 8 + lr) * QSTR
                    + (p * 16 + (lmat >> 1) * 8) * 2;
                uint32_t t[4], u[4];
                ldsm4t(t, rb);
                ldsm4t(u, rb + KVARR);
                mma_bf16(oacc[2 * p],     aph, t + 0);
                mma_bf16(oacc[2 * p],     apl, t + 0);
                mma_bf16(oacc[2 * p],     aph, u + 0);
                mma_bf16(oacc[2 * p + 1], aph, t + 2);
                mma_bf16(oacc[2 * p + 1], apl, t + 2);
                mma_bf16(oacc[2 * p + 1], aph, u + 2);
            }
        }
        __syncthreads();
    }

    // --- epilogue: O / l, written pre-split for the w_o GEMM ---
    float i0 = 1.f / lrow0, i1 = 1.f / lrow1;
    __nv_bfloat16* Xh = g_Xh + (rowbase + q0) * DMODEL + hoff;
    __nv_bfloat16* Xl = g_Xl + (rowbase + q0) * DMODEL + hoff;
    const int rl0 = qrow + (lane >> 2);
    #pragma unroll
    for (int nj = 0; nj < 8; nj++) {
        int col = nj * 8 + (lane & 3) * 2;
        float c0 = oacc[nj][0] * i0, c1 = oacc[nj][1] * i0;
        float c2 = oacc[nj][2] * i1, c3 = oacc[nj][3] * i1;
        float h0 = bf16rnd(c0), h1 = bf16rnd(c1);
        float h2 = bf16rnd(c2), h3 = bf16rnd(c3);
        *(uint32_t*)(Xh + (size_t)rl0 * DMODEL + col)       = pack_bf16x2(h0, h1);
        *(uint32_t*)(Xl + (size_t)rl0 * DMODEL + col)       = pack_bf16x2(c0 - h0, c1 - h1);
        *(uint32_t*)(Xh + (size_t)(rl0 + 8) * DMODEL + col) = pack_bf16x2(h2, h3);
        *(uint32_t*)(Xl + (size_t)(rl0 + 8) * DMODEL + col) = pack_bf16x2(c2 - h2, c3 - h3);
    }
}

// ---------------------------------------------------------------------------
extern "C" void kernel_launch(void* const* d_in, const int* in_sizes, int n_in,
                              void* d_out, int out_size)
{
    const float* q  = (const float*)d_in[0];
    const float* k  = (const float*)d_in[1];
    const float* v  = (const float*)d_in[2];
    const int* mask = (const int*)d_in[3];
    const float* w[4] = { (const float*)d_in[4], (const float*)d_in[5],
                          (const float*)d_in[6], (const float*)d_in[7] };
    float* out = (float*)d_out;

    const int M = in_sizes[0] / DMODEL;                       // B*S = 4096
    const int S = (int)(((long long)in_sizes[3]) / M);        // 2048
    const int B = M / S;                                      // 2

    __nv_bfloat16 *inh, *inl, *wwh, *wwl;
    __nv_bfloat16 *qh, *ql, *kh, *kl, *vh, *vl, *xh, *xl;
    uint32_t* mb;
    cudaGetSymbolAddress((void**)&inh, g_INh);
    cudaGetSymbolAddress((void**)&inl, g_INl);
    cudaGetSymbolAddress((void**)&wwh, g_WWh);
    cudaGetSymbolAddress((void**)&wwl, g_WWl);
    cudaGetSymbolAddress((void**)&qh, g_Qh);
    cudaGetSymbolAddress((void**)&ql, g_Ql);
    cudaGetSymbolAddress((void**)&kh, g_Kh);
    cudaGetSymbolAddress((void**)&kl, g_Kl);
    cudaGetSymbolAddress((void**)&vh, g_Vh);
    cudaGetSymbolAddress((void**)&vl, g_Vl);
    cudaGetSymbolAddress((void**)&xh, g_Xh);
    cudaGetSymbolAddress((void**)&xl, g_Xl);
    cudaGetSymbolAddress((void**)&mb, g_Mb);

    cudaFuncSetAttribute(gemm_qkv,
                         cudaFuncAttributeMaxDynamicSharedMemorySize, GEMM_SMEM);
    cudaFuncSetAttribute(gemm_out,
                         cudaFuncAttributeMaxDynamicSharedMemorySize, GEMM_SMEM);
    cudaFuncSetAttribute(flash_attn_tc,
                         cudaFuncAttributeMaxDynamicSharedMemorySize, ATTN_SMEM);

    const int AE = M * DMODEL;          // 4M activation elements
    const int WE = DMODEL * DMODEL;     // 1M weight elements
    const float* act[3] = { q, k, v };

    // --- split inputs + compress mask ---
    for (int i = 0; i < 3; i++)
        split_f32<<<AE / 1024, 256>>>((const float4*)act[i],
                                      (uint2*)(inh + (size_t)i * AE),
                                      (uint2*)(inl + (size_t)i * AE), AE / 4);
    for (int i = 0; i < 4; i++)
        split_f32<<<WE / 1024, 256>>>((const float4*)w[i],
                                      (uint2*)(wwh + (size_t)i * WE),
                                      (uint2*)(wwl + (size_t)i * WE), WE / 4);
    mask_bits<<<(B * S * S) / 8192, 256>>>(mask, mb);

    const float qscale = 0.125f * 1.44269504f;  // 1/sqrt(64) * log2(e)

    // --- merged QKV projections ---
    Batch3 bt;
    bt.g[0] = { inh,          inl,          wwh,          wwl,          qh, ql, qscale };
    bt.g[1] = { inh + AE,     inl + AE,     wwh + WE,     wwl + WE,     kh, kl, 1.f };
    bt.g[2] = { inh + 2 * AE, inl + 2 * AE, wwh + 2 * WE, wwl + 2 * WE, vh, vl, 1.f };
    dim3 gq(DMODEL / 128, M / 128, 3);
    gemm_qkv<<<gq, 256, GEMM_SMEM>>>(bt, M, DMODEL, DMODEL);

    dim3 ga(S / 128, NHEADS, B);
    flash_attn_tc<<<ga, 256, ATTN_SMEM>>>(S);

    dim3 gg(DMODEL / 128, M / 128);
    gemm_out<<<gg, 256, GEMM_SMEM>>>(xh, xl, wwh + 3 * WE, wwl + 3 * WE,
                                     out, M, DMODEL, DMODEL);
}